// round 2
// baseline (speedup 1.0000x reference)
#include <cuda_runtime.h>
#include <math.h>

#define TT 512
#define BB 64
#define II 1024
#define HH 1024
#define BH (BB*HH)          // 65536
#define NBLK 128            // persistent grid size (<= SM count, all co-resident)

// ---------------- device scratch (no allocations allowed) ----------------
__device__ float g_xz[(size_t)TT*BH];   // x @ Wzi^T + bzi + bzh
__device__ float g_xr[(size_t)TT*BH];
__device__ float g_xc[(size_t)TT*BH];
__device__ float g_h[BH];               // current hidden
__device__ float g_z[BH];               // update gate
__device__ float g_rh[BH];              // r * h

// grid barrier state: monotonic 64-bit, never reset -> no reset races,
// deterministic across graph replays (wraps after ~1e19 arrivals).
__device__ unsigned long long g_arrive = 0;
__device__ volatile unsigned long long g_release = 0;

__device__ __forceinline__ void grid_barrier() {
    __syncthreads();
    if (threadIdx.x == 0) {
        __threadfence();
        unsigned long long tok = atomicAdd(&g_arrive, 1ULL);
        unsigned long long gen = tok / NBLK;
        if ((tok % NBLK) == (NBLK - 1)) {
            g_release = gen + 1;
        } else {
            while (g_release < gen + 1) { }
        }
        __threadfence();
    }
    __syncthreads();
}

// ---------------- input projections: out[m,n] = x[m,:].W[n,:] + b1[n]+b2[n] --
// M = T*B = 32768, N = H = 1024, K = I = 1024. 128x128 tile, BK=16, 8x8 micro.
#define BM 128
#define BN 128
#define BK 16

__global__ __launch_bounds__(256, 2)
void gru_input_proj(const float* __restrict__ x,
                    const float* __restrict__ Wzi, const float* __restrict__ bzi, const float* __restrict__ bzh,
                    const float* __restrict__ Wri, const float* __restrict__ bri, const float* __restrict__ brh,
                    const float* __restrict__ Wci, const float* __restrict__ bci, const float* __restrict__ bch)
{
    const int gate = blockIdx.z;
    const float* W; const float* b1; const float* b2; float* out;
    if (gate == 0)      { W = Wzi; b1 = bzi; b2 = bzh; out = g_xz; }
    else if (gate == 1) { W = Wri; b1 = bri; b2 = brh; out = g_xr; }
    else                { W = Wci; b1 = bci; b2 = bch; out = g_xc; }

    __shared__ float As[BK][BM];
    __shared__ float Bs[BK][BN];

    const int m0 = blockIdx.y * BM;
    const int n0 = blockIdx.x * BN;
    const int tid = threadIdx.x;
    const int tx = tid & 15;
    const int ty = tid >> 4;

    float acc[8][8];
#pragma unroll
    for (int i = 0; i < 8; i++)
#pragma unroll
        for (int j = 0; j < 8; j++) acc[i][j] = 0.f;

    for (int k0 = 0; k0 < II; k0 += BK) {
#pragma unroll
        for (int i = 0; i < 2; i++) {
            int slot = tid + i * 256;
            int r  = slot >> 2;
            int kq = (slot & 3) << 2;
            float4 va = *(const float4*)&x[(size_t)(m0 + r) * II + k0 + kq];
            As[kq + 0][r] = va.x; As[kq + 1][r] = va.y; As[kq + 2][r] = va.z; As[kq + 3][r] = va.w;
            float4 vb = *(const float4*)&W[(size_t)(n0 + r) * II + k0 + kq];
            Bs[kq + 0][r] = vb.x; Bs[kq + 1][r] = vb.y; Bs[kq + 2][r] = vb.z; Bs[kq + 3][r] = vb.w;
        }
        __syncthreads();

#pragma unroll
        for (int kk = 0; kk < BK; kk++) {
            float a[8], b[8];
            float4 a0 = *(const float4*)&As[kk][ty * 8];
            float4 a1 = *(const float4*)&As[kk][ty * 8 + 4];
            float4 b0 = *(const float4*)&Bs[kk][tx * 8];
            float4 b1v = *(const float4*)&Bs[kk][tx * 8 + 4];
            a[0]=a0.x;a[1]=a0.y;a[2]=a0.z;a[3]=a0.w;a[4]=a1.x;a[5]=a1.y;a[6]=a1.z;a[7]=a1.w;
            b[0]=b0.x;b[1]=b0.y;b[2]=b0.z;b[3]=b0.w;b[4]=b1v.x;b[5]=b1v.y;b[6]=b1v.z;b[7]=b1v.w;
#pragma unroll
            for (int i = 0; i < 8; i++)
#pragma unroll
                for (int j = 0; j < 8; j++)
                    acc[i][j] += a[i] * b[j];
        }
        __syncthreads();
    }

    float bb[8];
#pragma unroll
    for (int j = 0; j < 8; j++) {
        int n = n0 + tx * 8 + j;
        bb[j] = b1[n] + b2[n];
    }
#pragma unroll
    for (int i = 0; i < 8; i++) {
        int m = m0 + ty * 8 + i;
#pragma unroll
        for (int jq = 0; jq < 2; jq++) {
            float4 v;
            v.x = acc[i][jq * 4 + 0] + bb[jq * 4 + 0];
            v.y = acc[i][jq * 4 + 1] + bb[jq * 4 + 1];
            v.z = acc[i][jq * 4 + 2] + bb[jq * 4 + 2];
            v.w = acc[i][jq * 4 + 3] + bb[jq * 4 + 3];
            *(float4*)&out[(size_t)m * HH + n0 + tx * 8 + jq * 4] = v;
        }
    }
}

// ---------------- persistent recurrence kernel ----------------
// One launch runs all 512 steps. Per step:
//   Phase A: 128 blocks = {z,r} x 64 col-tiles; block = 64 batch x 16 cols,
//            K=1024, full dot; epilogue applies sigmoid, writes g_z / g_rh.
//   Phase B: 128 blocks = 2 batch-halves x 64 col-tiles; block = 32 x 16;
//            epilogue tanh + gate blend, writes g_h and out[t].
// smem: h slab stride 68 (phase A, 64 rows) / 34 (phase B, 32 rows), W stride 17.
#define SMEM_WOFF (64*68)

__global__ __launch_bounds__(256)
void gru_recurrence(const float* __restrict__ hidden,
                    const float* __restrict__ Wzh,
                    const float* __restrict__ Wrh,
                    const float* __restrict__ Wch,
                    float* __restrict__ out)
{
    __shared__ float sm[64*68 + 64*17];
    float* wS = sm + SMEM_WOFF;
    const int tid = threadIdx.x;
    const int bid = blockIdx.x;

    // init hidden state
    for (int i = bid * 256 + tid; i < BH; i += NBLK * 256) g_h[i] = hidden[i];
    grid_barrier();

    const int tx = tid & 15;          // column within 16-col tile
    const int ty = tid >> 4;          // 0..15
    const int wj = tid >> 4;          // W loader: col 0..15
    const int wq = tid & 15;          // W loader: k quad

    for (int t = 0; t < TT; t++) {
        // ================= Phase A: z and r gates =================
        {
            const int gate = bid >> 6;                 // 0 = z, 1 = r
            const int n0 = (bid & 63) * 16;
            const float* __restrict__ W = gate ? Wrh : Wzh;
            const int lb = tid & 63;                   // h loader: batch row
            const int lh = tid >> 6;                   // h loader: k sixteenth
            float acc[4] = {0.f, 0.f, 0.f, 0.f};

            for (int k0 = 0; k0 < HH; k0 += 64) {
                // stage h slab [64k x 64b], k-major, stride 68
#pragma unroll
                for (int j = 0; j < 4; j++) {
                    int kk = lh * 16 + j * 4;
                    float4 v = *(const float4*)&g_h[lb * HH + k0 + kk];
                    sm[(kk+0)*68 + lb] = v.x; sm[(kk+1)*68 + lb] = v.y;
                    sm[(kk+2)*68 + lb] = v.z; sm[(kk+3)*68 + lb] = v.w;
                }
                // stage W slab [64k x 16n], stride 17
                {
                    int kk = wq * 4;
                    float4 v = *(const float4*)&W[(size_t)(n0 + wj) * HH + k0 + kk];
                    wS[(kk+0)*17 + wj] = v.x; wS[(kk+1)*17 + wj] = v.y;
                    wS[(kk+2)*17 + wj] = v.z; wS[(kk+3)*17 + wj] = v.w;
                }
                __syncthreads();
#pragma unroll
                for (int k = 0; k < 64; k++) {
                    float4 h4 = *(const float4*)&sm[k * 68 + ty * 4];
                    float w = wS[k * 17 + tx];
                    acc[0] += h4.x * w; acc[1] += h4.y * w;
                    acc[2] += h4.z * w; acc[3] += h4.w * w;
                }
                __syncthreads();
            }
            const float* __restrict__ xg = gate ? g_xr : g_xz;
#pragma unroll
            for (int i = 0; i < 4; i++) {
                int idx = (ty * 4 + i) * HH + n0 + tx;
                float a = acc[i] + xg[(size_t)t * BH + idx];
                float s = 1.f / (1.f + __expf(-a));
                if (gate) g_rh[idx] = s * g_h[idx];
                else      g_z[idx]  = s;
            }
        }
        grid_barrier();

        // ================= Phase B: candidate + blend =================
        {
            const int bh = bid >> 6;                   // batch half
            const int n0 = (bid & 63) * 16;
            const int lb = tid & 31;                   // h loader: batch row
            const int lp = tid >> 5;                   // h loader: k eighth
            float acc0 = 0.f, acc1 = 0.f;

            for (int k0 = 0; k0 < HH; k0 += 64) {
                // stage rh slab [64k x 32b], stride 34
#pragma unroll
                for (int j = 0; j < 2; j++) {
                    int kk = lp * 8 + j * 4;
                    float4 v = *(const float4*)&g_rh[(size_t)(bh * 32 + lb) * HH + k0 + kk];
                    sm[(kk+0)*34 + lb] = v.x; sm[(kk+1)*34 + lb] = v.y;
                    sm[(kk+2)*34 + lb] = v.z; sm[(kk+3)*34 + lb] = v.w;
                }
                {
                    int kk = wq * 4;
                    float4 v = *(const float4*)&Wch[(size_t)(n0 + wj) * HH + k0 + kk];
                    wS[(kk+0)*17 + wj] = v.x; wS[(kk+1)*17 + wj] = v.y;
                    wS[(kk+2)*17 + wj] = v.z; wS[(kk+3)*17 + wj] = v.w;
                }
                __syncthreads();
#pragma unroll
                for (int k = 0; k < 64; k++) {
                    float2 h2 = *(const float2*)&sm[k * 34 + ty * 2];
                    float w = wS[k * 17 + tx];
                    acc0 += h2.x * w; acc1 += h2.y * w;
                }
                __syncthreads();
            }
#pragma unroll
            for (int i = 0; i < 2; i++) {
                int b = bh * 32 + ty * 2 + i;
                int idx = b * HH + n0 + tx;
                float a = (i ? acc1 : acc0) + g_xc[(size_t)t * BH + idx];
                float c = tanhf(a);
                float z = g_z[idx];
                float hn = (1.f - z) * g_h[idx] + z * c;
                g_h[idx] = hn;
                out[(size_t)t * BH + idx] = hn;
                if (t == TT - 1) out[(size_t)TT * BH + idx] = hn;
            }
        }
        grid_barrier();
    }
}

// ---------------- launch ----------------
extern "C" void kernel_launch(void* const* d_in, const int* in_sizes, int n_in,
                              void* d_out, int out_size)
{
    const float* x      = (const float*)d_in[0];
    const float* hidden = (const float*)d_in[1];
    const float* Wzi = (const float*)d_in[2];  const float* bzi = (const float*)d_in[3];
    const float* Wzh = (const float*)d_in[4];  const float* bzh = (const float*)d_in[5];
    const float* Wri = (const float*)d_in[6];  const float* bri = (const float*)d_in[7];
    const float* Wrh = (const float*)d_in[8];  const float* brh = (const float*)d_in[9];
    const float* Wci = (const float*)d_in[10]; const float* bci = (const float*)d_in[11];
    const float* Wch = (const float*)d_in[12]; const float* bch = (const float*)d_in[13];
    float* out = (float*)d_out;

    dim3 gp(HH / BN, (TT * BB) / BM, 3);
    gru_input_proj<<<gp, 256>>>(x, Wzi, bzi, bzh, Wri, bri, brh, Wci, bci, bch);

    gru_recurrence<<<NBLK, 256>>>(hidden, Wzh, Wrh, Wch, out);
}

// round 3
// speedup vs baseline: 1.3943x; 1.3943x over previous
#include <cuda_runtime.h>
#include <math.h>

#define TT 512
#define BB 64
#define II 1024
#define HH 1024
#define BH (BB*HH)          // 65536
#define NBLK 128            // persistent grid (1 block/SM, all co-resident)

// ---------------- device scratch ----------------
__device__ float g_xz[(size_t)TT*BH];
__device__ float g_xr[(size_t)TT*BH];
__device__ float g_xc[(size_t)TT*BH];
__device__ float g_h[BH];
__device__ float g_z[BH];
__device__ float g_rh[BH];

// monotonic grid barrier (never reset -> replay-deterministic)
__device__ unsigned long long g_arrive = 0;
__device__ volatile unsigned long long g_release = 0;

__device__ __forceinline__ void grid_barrier() {
    __syncthreads();
    if (threadIdx.x == 0) {
        __threadfence();
        unsigned long long tok = atomicAdd(&g_arrive, 1ULL);
        unsigned long long gen = tok / NBLK;
        if ((tok % NBLK) == (NBLK - 1)) {
            g_release = gen + 1;
        } else {
            while (g_release < gen + 1) { }
        }
        __threadfence();
    }
    __syncthreads();
}

// ---------------- input projections (validated in R2) ----------------
#define BM 128
#define BN 128
#define BK 16

__global__ __launch_bounds__(256, 2)
void gru_input_proj(const float* __restrict__ x,
                    const float* __restrict__ Wzi, const float* __restrict__ bzi, const float* __restrict__ bzh,
                    const float* __restrict__ Wri, const float* __restrict__ bri, const float* __restrict__ brh,
                    const float* __restrict__ Wci, const float* __restrict__ bci, const float* __restrict__ bch)
{
    const int gate = blockIdx.z;
    const float* W; const float* b1; const float* b2; float* out;
    if (gate == 0)      { W = Wzi; b1 = bzi; b2 = bzh; out = g_xz; }
    else if (gate == 1) { W = Wri; b1 = bri; b2 = brh; out = g_xr; }
    else                { W = Wci; b1 = bci; b2 = bch; out = g_xc; }

    __shared__ float As[BK][BM];
    __shared__ float Bs[BK][BN];

    const int m0 = blockIdx.y * BM;
    const int n0 = blockIdx.x * BN;
    const int tid = threadIdx.x;
    const int tx = tid & 15;
    const int ty = tid >> 4;

    float acc[8][8];
#pragma unroll
    for (int i = 0; i < 8; i++)
#pragma unroll
        for (int j = 0; j < 8; j++) acc[i][j] = 0.f;

    for (int k0 = 0; k0 < II; k0 += BK) {
#pragma unroll
        for (int i = 0; i < 2; i++) {
            int slot = tid + i * 256;
            int r  = slot >> 2;
            int kq = (slot & 3) << 2;
            float4 va = *(const float4*)&x[(size_t)(m0 + r) * II + k0 + kq];
            As[kq + 0][r] = va.x; As[kq + 1][r] = va.y; As[kq + 2][r] = va.z; As[kq + 3][r] = va.w;
            float4 vb = *(const float4*)&W[(size_t)(n0 + r) * II + k0 + kq];
            Bs[kq + 0][r] = vb.x; Bs[kq + 1][r] = vb.y; Bs[kq + 2][r] = vb.z; Bs[kq + 3][r] = vb.w;
        }
        __syncthreads();

#pragma unroll
        for (int kk = 0; kk < BK; kk++) {
            float a[8], b[8];
            float4 a0 = *(const float4*)&As[kk][ty * 8];
            float4 a1 = *(const float4*)&As[kk][ty * 8 + 4];
            float4 b0 = *(const float4*)&Bs[kk][tx * 8];
            float4 b1v = *(const float4*)&Bs[kk][tx * 8 + 4];
            a[0]=a0.x;a[1]=a0.y;a[2]=a0.z;a[3]=a0.w;a[4]=a1.x;a[5]=a1.y;a[6]=a1.z;a[7]=a1.w;
            b[0]=b0.x;b[1]=b0.y;b[2]=b0.z;b[3]=b0.w;b[4]=b1v.x;b[5]=b1v.y;b[6]=b1v.z;b[7]=b1v.w;
#pragma unroll
            for (int i = 0; i < 8; i++)
#pragma unroll
                for (int j = 0; j < 8; j++)
                    acc[i][j] += a[i] * b[j];
        }
        __syncthreads();
    }

    float bb[8];
#pragma unroll
    for (int j = 0; j < 8; j++) {
        int n = n0 + tx * 8 + j;
        bb[j] = b1[n] + b2[n];
    }
#pragma unroll
    for (int i = 0; i < 8; i++) {
        int m = m0 + ty * 8 + i;
#pragma unroll
        for (int jq = 0; jq < 2; jq++) {
            float4 v;
            v.x = acc[i][jq * 4 + 0] + bb[jq * 4 + 0];
            v.y = acc[i][jq * 4 + 1] + bb[jq * 4 + 1];
            v.z = acc[i][jq * 4 + 2] + bb[jq * 4 + 2];
            v.w = acc[i][jq * 4 + 3] + bb[jq * 4 + 3];
            *(float4*)&out[(size_t)m * HH + n0 + tx * 8 + jq * 4] = v;
        }
    }
}

// ---------------- persistent recurrence: weight-stationary ----------------
// 128 blocks x 256 threads. Block owns 8 cols of Wzh,Wrh,Wch in smem (96KB).
// Phase A: C[64b x 16n] (z|r), warp-K-split, lane tile 8x4.
// Phase B: C[64b x 8n] (cand), lane tile 4x4.
// h/rh staged in 128-k tiles, double buffered, prefetch via registers.
//
// dynamic smem layout (floats):
//   wzr : 1024*16      = 16384   (k-major, col = gate*8 + j)
//   wc  : 1024*8       =  8192
//   hbuf: 2 * 128*68   = 17408   (hbuf[buf][kk*68 + b]); buf0 reused as
//                                 partial-reduction buffer (needs 8192 floats)
#define SM_WZR   0
#define SM_WC    16384
#define SM_HBUF  (16384 + 8192)
#define HSTRIDE  68
#define HBUFSZ   (128*HSTRIDE)
#define SMEM_FLOATS (SM_HBUF + 2*HBUFSZ)

__global__ __launch_bounds__(256, 1)
void gru_recurrence(const float* __restrict__ hidden,
                    const float* __restrict__ Wzh,
                    const float* __restrict__ Wrh,
                    const float* __restrict__ Wch,
                    float* __restrict__ out)
{
    extern __shared__ float sm[];
    float* wzr  = sm + SM_WZR;
    float* wc   = sm + SM_WC;
    float* hbuf = sm + SM_HBUF;
    float* pbuf = hbuf;                 // reduction staging (aliases hbuf[0])

    const int tid  = threadIdx.x;
    const int bid  = blockIdx.x;
    const int n0   = bid * 8;           // this block's output-column base
    const int warp = tid >> 5;
    const int lane = tid & 31;

    // ---- preload weights into smem (once) ----
    {
        int j = (tid >> 5) & 7;         // row (column of W^T) 0..7
#pragma unroll
        for (int g = 0; g < 2; g++) {
            const float* W = g ? Wrh : Wzh;
#pragma unroll
            for (int i = 0; i < 8; i++) {
                int k = i * 128 + lane * 4;
                float4 v = *(const float4*)&W[(size_t)(n0 + j) * HH + k];
                wzr[(k+0)*16 + g*8 + j] = v.x; wzr[(k+1)*16 + g*8 + j] = v.y;
                wzr[(k+2)*16 + g*8 + j] = v.z; wzr[(k+3)*16 + g*8 + j] = v.w;
            }
        }
#pragma unroll
        for (int i = 0; i < 8; i++) {
            int k = i * 128 + lane * 4;
            float4 v = *(const float4*)&Wch[(size_t)(n0 + j) * HH + k];
            wc[(k+0)*8 + j] = v.x; wc[(k+1)*8 + j] = v.y;
            wc[(k+2)*8 + j] = v.z; wc[(k+3)*8 + j] = v.w;
        }
    }

    // ---- init hidden ----
    for (int i = bid * 256 + tid; i < BH; i += NBLK * 256) g_h[i] = hidden[i];
    grid_barrier();   // also covers the smem weight preload within the block

    // staging loader coords: thread loads 8 float4 of row b, k-range kg*32..+31
    const int lb = tid & 63;
    const int kg = tid >> 6;

    for (int t = 0; t < TT; t++) {
        // ====================== Phase A: z and r ======================
        {
            const int bg = lane >> 2;       // 8 batch rows of 8
            const int ng = lane & 3;        // 4 col groups of 4 (0,1=z 2,3=r)
            float acc[8][4];
#pragma unroll
            for (int i = 0; i < 8; i++)
#pragma unroll
                for (int j = 0; j < 4; j++) acc[i][j] = 0.f;

            float4 pf[8];
            // prologue: tile 0
#pragma unroll
            for (int j = 0; j < 8; j++)
                pf[j] = *(const float4*)&g_h[lb * HH + kg * 32 + j * 4];
#pragma unroll
            for (int j = 0; j < 8; j++) {
                int kk = kg * 32 + j * 4;
                hbuf[(kk+0)*HSTRIDE + lb] = pf[j].x; hbuf[(kk+1)*HSTRIDE + lb] = pf[j].y;
                hbuf[(kk+2)*HSTRIDE + lb] = pf[j].z; hbuf[(kk+3)*HSTRIDE + lb] = pf[j].w;
            }

            for (int kt = 0; kt < 8; kt++) {
                __syncthreads();
                float* cur = hbuf + (kt & 1) * HBUFSZ;
                if (kt < 7) {
#pragma unroll
                    for (int j = 0; j < 8; j++)
                        pf[j] = *(const float4*)&g_h[lb * HH + (kt+1) * 128 + kg * 32 + j * 4];
                }
                // compute: this warp's 16-k slice of the tile
                const int kbase = kt * 128 + warp * 16;
#pragma unroll
                for (int kk = 0; kk < 16; kk++) {
                    const float* hrow = cur + (warp * 16 + kk) * HSTRIDE + bg * 8;
                    float4 h0 = *(const float4*)&hrow[0];
                    float4 h1 = *(const float4*)&hrow[4];
                    float4 wv = *(const float4*)&wzr[(kbase + kk) * 16 + ng * 4];
                    float hv[8] = {h0.x,h0.y,h0.z,h0.w,h1.x,h1.y,h1.z,h1.w};
                    float wl[4] = {wv.x,wv.y,wv.z,wv.w};
#pragma unroll
                    for (int i = 0; i < 8; i++)
#pragma unroll
                        for (int j = 0; j < 4; j++)
                            acc[i][j] += hv[i] * wl[j];
                }
                if (kt < 7) {
                    float* nxt = hbuf + ((kt+1) & 1) * HBUFSZ;
#pragma unroll
                    for (int j = 0; j < 8; j++) {
                        int kk = kg * 32 + j * 4;
                        nxt[(kk+0)*HSTRIDE + lb] = pf[j].x; nxt[(kk+1)*HSTRIDE + lb] = pf[j].y;
                        nxt[(kk+2)*HSTRIDE + lb] = pf[j].z; nxt[(kk+3)*HSTRIDE + lb] = pf[j].w;
                    }
                }
            }
            // store partials (into buf0 region; last compute used buf1)
#pragma unroll
            for (int i = 0; i < 8; i++) {
                float4 v; v.x = acc[i][0]; v.y = acc[i][1]; v.z = acc[i][2]; v.w = acc[i][3];
                *(float4*)&pbuf[warp * 1024 + (bg * 8 + i) * 16 + ng * 4] = v;
            }
            __syncthreads();

            // reduce + epilogue: thread -> (b, 4 cols)
            {
                int b  = tid & 63;
                int c0 = (tid >> 6) * 4;      // 0,4 = z ; 8,12 = r
                float4 s = *(const float4*)&pbuf[b * 16 + c0];
#pragma unroll
                for (int w = 1; w < 8; w++) {
                    float4 p = *(const float4*)&pbuf[w * 1024 + b * 16 + c0];
                    s.x += p.x; s.y += p.y; s.z += p.z; s.w += p.w;
                }
                if (c0 < 8) {
                    float4 xg = *(const float4*)&g_xz[(size_t)t * BH + b * HH + n0 + c0];
                    float4 r;
                    r.x = 1.f / (1.f + __expf(-(s.x + xg.x)));
                    r.y = 1.f / (1.f + __expf(-(s.y + xg.y)));
                    r.z = 1.f / (1.f + __expf(-(s.z + xg.z)));
                    r.w = 1.f / (1.f + __expf(-(s.w + xg.w)));
                    *(float4*)&g_z[b * HH + n0 + c0] = r;
                } else {
                    int c = c0 - 8;
                    float4 xg = *(const float4*)&g_xr[(size_t)t * BH + b * HH + n0 + c];
                    float4 hv = *(const float4*)&g_h[b * HH + n0 + c];
                    float4 r;
                    r.x = hv.x / (1.f + __expf(-(s.x + xg.x)));
                    r.y = hv.y / (1.f + __expf(-(s.y + xg.y)));
                    r.z = hv.z / (1.f + __expf(-(s.z + xg.z)));
                    r.w = hv.w / (1.f + __expf(-(s.w + xg.w)));
                    *(float4*)&g_rh[b * HH + n0 + c] = r;
                }
            }
        }
        grid_barrier();

        // ====================== Phase B: candidate + blend ======================
        {
            const int bg = lane >> 1;       // 16 batch rows of 4
            const int ng = lane & 1;        // 2 col groups of 4
            float acc[4][4];
#pragma unroll
            for (int i = 0; i < 4; i++)
#pragma unroll
                for (int j = 0; j < 4; j++) acc[i][j] = 0.f;

            float4 pf[8];
#pragma unroll
            for (int j = 0; j < 8; j++)
                pf[j] = *(const float4*)&g_rh[lb * HH + kg * 32 + j * 4];
#pragma unroll
            for (int j = 0; j < 8; j++) {
                int kk = kg * 32 + j * 4;
                hbuf[(kk+0)*HSTRIDE + lb] = pf[j].x; hbuf[(kk+1)*HSTRIDE + lb] = pf[j].y;
                hbuf[(kk+2)*HSTRIDE + lb] = pf[j].z; hbuf[(kk+3)*HSTRIDE + lb] = pf[j].w;
            }

            for (int kt = 0; kt < 8; kt++) {
                __syncthreads();
                float* cur = hbuf + (kt & 1) * HBUFSZ;
                if (kt < 7) {
#pragma unroll
                    for (int j = 0; j < 8; j++)
                        pf[j] = *(const float4*)&g_rh[lb * HH + (kt+1) * 128 + kg * 32 + j * 4];
                }
                const int kbase = kt * 128 + warp * 16;
#pragma unroll
                for (int kk = 0; kk < 16; kk++) {
                    float4 h0 = *(const float4*)&cur[(warp * 16 + kk) * HSTRIDE + bg * 4];
                    float4 wv = *(const float4*)&wc[(kbase + kk) * 8 + ng * 4];
                    float hv[4] = {h0.x,h0.y,h0.z,h0.w};
                    float wl[4] = {wv.x,wv.y,wv.z,wv.w};
#pragma unroll
                    for (int i = 0; i < 4; i++)
#pragma unroll
                        for (int j = 0; j < 4; j++)
                            acc[i][j] += hv[i] * wl[j];
                }
                if (kt < 7) {
                    float* nxt = hbuf + ((kt+1) & 1) * HBUFSZ;
#pragma unroll
                    for (int j = 0; j < 8; j++) {
                        int kk = kg * 32 + j * 4;
                        nxt[(kk+0)*HSTRIDE + lb] = pf[j].x; nxt[(kk+1)*HSTRIDE + lb] = pf[j].y;
                        nxt[(kk+2)*HSTRIDE + lb] = pf[j].z; nxt[(kk+3)*HSTRIDE + lb] = pf[j].w;
                    }
                }
            }
#pragma unroll
            for (int i = 0; i < 4; i++) {
                float4 v; v.x = acc[i][0]; v.y = acc[i][1]; v.z = acc[i][2]; v.w = acc[i][3];
                *(float4*)&pbuf[warp * 512 + (bg * 4 + i) * 8 + ng * 4] = v;
            }
            __syncthreads();

            // reduce + epilogue: thread -> (b, 2 cols)
            {
                int b  = tid & 63;
                int c0 = (tid >> 6) * 2;
                float s0 = 0.f, s1 = 0.f;
#pragma unroll
                for (int w = 0; w < 8; w++) {
                    s0 += pbuf[w * 512 + b * 8 + c0 + 0];
                    s1 += pbuf[w * 512 + b * 8 + c0 + 1];
                }
                size_t base = (size_t)t * BH + b * HH + n0 + c0;
                int idx = b * HH + n0 + c0;
                float xc0 = g_xc[base + 0], xc1 = g_xc[base + 1];
                float z0 = g_z[idx + 0],   z1 = g_z[idx + 1];
                float h0 = g_h[idx + 0],   h1 = g_h[idx + 1];
                float c_0 = tanhf(s0 + xc0);
                float c_1 = tanhf(s1 + xc1);
                float hn0 = (1.f - z0) * h0 + z0 * c_0;
                float hn1 = (1.f - z1) * h1 + z1 * c_1;
                g_h[idx + 0] = hn0; g_h[idx + 1] = hn1;
                out[base + 0] = hn0; out[base + 1] = hn1;
                if (t == TT - 1) {
                    out[(size_t)TT * BH + idx + 0] = hn0;
                    out[(size_t)TT * BH + idx + 1] = hn1;
                }
            }
        }
        grid_barrier();
    }
}

// ---------------- launch ----------------
extern "C" void kernel_launch(void* const* d_in, const int* in_sizes, int n_in,
                              void* d_out, int out_size)
{
    const float* x      = (const float*)d_in[0];
    const float* hidden = (const float*)d_in[1];
    const float* Wzi = (const float*)d_in[2];  const float* bzi = (const float*)d_in[3];
    const float* Wzh = (const float*)d_in[4];  const float* bzh = (const float*)d_in[5];
    const float* Wri = (const float*)d_in[6];  const float* bri = (const float*)d_in[7];
    const float* Wrh = (const float*)d_in[8];  const float* brh = (const float*)d_in[9];
    const float* Wci = (const float*)d_in[10]; const float* bci = (const float*)d_in[11];
    const float* Wch = (const float*)d_in[12]; const float* bch = (const float*)d_in[13];
    float* out = (float*)d_out;

    dim3 gp(HH / BN, (TT * BB) / BM, 3);
    gru_input_proj<<<gp, 256>>>(x, Wzi, bzi, bzh, Wri, bri, brh, Wci, bci, bch);

    static int smem_set = 0;
    (void)smem_set;
    cudaFuncSetAttribute(gru_recurrence,
                         cudaFuncAttributeMaxDynamicSharedMemorySize,
                         SMEM_FLOATS * (int)sizeof(float));
    gru_recurrence<<<NBLK, 256, SMEM_FLOATS * sizeof(float)>>>(hidden, Wzh, Wrh, Wch, out);
}

// round 4
// speedup vs baseline: 2.0085x; 1.4405x over previous
#include <cuda_runtime.h>
#include <cuda_bf16.h>
#include <mma.h>
#include <math.h>

using namespace nvcuda;

#define TT 512
#define BB 64
#define II 1024
#define HH 1024
#define BH (BB*HH)          // 65536
#define NBLK 128            // persistent grid, 1 block/SM

// ---------------- device scratch ----------------
__device__ float g_xz[(size_t)TT*BH];
__device__ float g_xr[(size_t)TT*BH];
__device__ float g_xc[(size_t)TT*BH];
__device__ float g_h[BH];
__device__ float g_z[BH];
__device__ float g_rh[BH];

// monotonic grid barrier (validated R2/R3)
__device__ unsigned long long g_arrive = 0;
__device__ volatile unsigned long long g_release = 0;

__device__ __forceinline__ void grid_barrier() {
    __syncthreads();
    if (threadIdx.x == 0) {
        __threadfence();
        unsigned long long tok = atomicAdd(&g_arrive, 1ULL);
        unsigned long long gen = tok / NBLK;
        if ((tok % NBLK) == (NBLK - 1)) {
            g_release = gen + 1;
        } else {
            while (g_release < gen + 1) { }
        }
        __threadfence();
    }
    __syncthreads();
}

// ---------------- input projections (validated R2/R3) ----------------
#define BM 128
#define BN 128
#define BK 16

__global__ __launch_bounds__(256, 2)
void gru_input_proj(const float* __restrict__ x,
                    const float* __restrict__ Wzi, const float* __restrict__ bzi, const float* __restrict__ bzh,
                    const float* __restrict__ Wri, const float* __restrict__ bri, const float* __restrict__ brh,
                    const float* __restrict__ Wci, const float* __restrict__ bci, const float* __restrict__ bch)
{
    const int gate = blockIdx.z;
    const float* W; const float* b1; const float* b2; float* out;
    if (gate == 0)      { W = Wzi; b1 = bzi; b2 = bzh; out = g_xz; }
    else if (gate == 1) { W = Wri; b1 = bri; b2 = brh; out = g_xr; }
    else                { W = Wci; b1 = bci; b2 = bch; out = g_xc; }

    __shared__ float As[BK][BM];
    __shared__ float Bs[BK][BN];

    const int m0 = blockIdx.y * BM;
    const int n0 = blockIdx.x * BN;
    const int tid = threadIdx.x;
    const int tx = tid & 15;
    const int ty = tid >> 4;

    float acc[8][8];
#pragma unroll
    for (int i = 0; i < 8; i++)
#pragma unroll
        for (int j = 0; j < 8; j++) acc[i][j] = 0.f;

    for (int k0 = 0; k0 < II; k0 += BK) {
#pragma unroll
        for (int i = 0; i < 2; i++) {
            int slot = tid + i * 256;
            int r  = slot >> 2;
            int kq = (slot & 3) << 2;
            float4 va = *(const float4*)&x[(size_t)(m0 + r) * II + k0 + kq];
            As[kq + 0][r] = va.x; As[kq + 1][r] = va.y; As[kq + 2][r] = va.z; As[kq + 3][r] = va.w;
            float4 vb = *(const float4*)&W[(size_t)(n0 + r) * II + k0 + kq];
            Bs[kq + 0][r] = vb.x; Bs[kq + 1][r] = vb.y; Bs[kq + 2][r] = vb.z; Bs[kq + 3][r] = vb.w;
        }
        __syncthreads();

#pragma unroll
        for (int kk = 0; kk < BK; kk++) {
            float a[8], b[8];
            float4 a0 = *(const float4*)&As[kk][ty * 8];
            float4 a1 = *(const float4*)&As[kk][ty * 8 + 4];
            float4 b0 = *(const float4*)&Bs[kk][tx * 8];
            float4 b1v = *(const float4*)&Bs[kk][tx * 8 + 4];
            a[0]=a0.x;a[1]=a0.y;a[2]=a0.z;a[3]=a0.w;a[4]=a1.x;a[5]=a1.y;a[6]=a1.z;a[7]=a1.w;
            b[0]=b0.x;b[1]=b0.y;b[2]=b0.z;b[3]=b0.w;b[4]=b1v.x;b[5]=b1v.y;b[6]=b1v.z;b[7]=b1v.w;
#pragma unroll
            for (int i = 0; i < 8; i++)
#pragma unroll
                for (int j = 0; j < 8; j++)
                    acc[i][j] += a[i] * b[j];
        }
        __syncthreads();
    }

    float bb[8];
#pragma unroll
    for (int j = 0; j < 8; j++) {
        int n = n0 + tx * 8 + j;
        bb[j] = b1[n] + b2[n];
    }
#pragma unroll
    for (int i = 0; i < 8; i++) {
        int m = m0 + ty * 8 + i;
#pragma unroll
        for (int jq = 0; jq < 2; jq++) {
            float4 v;
            v.x = acc[i][jq * 4 + 0] + bb[jq * 4 + 0];
            v.y = acc[i][jq * 4 + 1] + bb[jq * 4 + 1];
            v.z = acc[i][jq * 4 + 2] + bb[jq * 4 + 2];
            v.w = acc[i][jq * 4 + 3] + bb[jq * 4 + 3];
            *(float4*)&out[(size_t)m * HH + n0 + tx * 8 + jq * 4] = v;
        }
    }
}

// ---------------- tensor-core persistent recurrence ----------------
// bf16 split (hi/lo) wmma m16n16k16, fp32 accumulate, 3 mma passes.
// smem (bytes):
//   wzr_hi/lo : 2 x 1024x16 bf16 = 65536
//   wc_hi/lo  : 2 x 1024x16 bf16 = 65536
//   hbuf      : 2 buffers x (hi+lo) x [64][KPAD] bf16 = 69632
//   pbuf (fp32 partials, 8KB) aliases hbuf buffer 0
#define KPAD 136
#define HMAT (64*KPAD)                 // bf16 elems per matrix
#define SMEM_BYTES (65536 + 65536 + 2*2*HMAT*2)

typedef wmma::fragment<wmma::matrix_a, 16, 16, 16, __nv_bfloat16, wmma::row_major> FragA;
typedef wmma::fragment<wmma::matrix_b, 16, 16, 16, __nv_bfloat16, wmma::row_major> FragB;
typedef wmma::fragment<wmma::accumulator, 16, 16, 16, float> FragC;

// convert 8 fp32 -> 8 bf16 hi + 8 bf16 lo packed as uint4
__device__ __forceinline__ void cvt8(float4 a, float4 b, uint4* hi4, uint4* lo4)
{
    union { __nv_bfloat16 h[8]; uint4 u; } H, L;
    float f[8] = {a.x, a.y, a.z, a.w, b.x, b.y, b.z, b.w};
#pragma unroll
    for (int j = 0; j < 8; j++) {
        __nv_bfloat16 hv = __float2bfloat16(f[j]);
        H.h[j] = hv;
        L.h[j] = __float2bfloat16(f[j] - __bfloat162float(hv));
    }
    *hi4 = H.u; *lo4 = L.u;
}

__global__ __launch_bounds__(256, 1)
void gru_recurrence(const float* __restrict__ hidden,
                    const float* __restrict__ Wzh,
                    const float* __restrict__ Wrh,
                    const float* __restrict__ Wch,
                    float* __restrict__ out)
{
    extern __shared__ char smem[];
    __nv_bfloat16* wzr_h = (__nv_bfloat16*)smem;
    __nv_bfloat16* wzr_l = wzr_h + 1024 * 16;
    __nv_bfloat16* wc_h  = wzr_l + 1024 * 16;
    __nv_bfloat16* wc_l  = wc_h  + 1024 * 16;
    __nv_bfloat16* hb    = wc_l  + 1024 * 16;   // 2 x (hi, lo) [64][KPAD]
    float* pbuf = (float*)hb;                    // aliases buffer 0

    const int tid  = threadIdx.x;
    const int bid  = blockIdx.x;
    const int warp = tid >> 5;
    const int lane = tid & 31;

    const int gate = bid >> 6;                   // phase A: 0=z, 1=r
    const int n0g  = (bid & 63) * 16;            // phase A col base (within gate)
    const int n0c  = (bid & 63) * 16;            // phase B col base
    const int bh   = bid >> 6;                   // phase B batch half

    // ---- one-time: convert this block's weight slices to bf16 hi/lo in smem ----
    {
        const float* WA = gate ? Wrh : Wzh;
        int j  = tid >> 4;        // 0..15 col
        int kc = tid & 15;        // k chunk
#pragma unroll
        for (int i = 0; i < 8; i++) {
            int k = i * 128 + kc * 8;
            float4 v0 = *(const float4*)&WA[(size_t)(n0g + j) * HH + k];
            float4 v1 = *(const float4*)&WA[(size_t)(n0g + j) * HH + k + 4];
            float f[8] = {v0.x,v0.y,v0.z,v0.w,v1.x,v1.y,v1.z,v1.w};
#pragma unroll
            for (int q = 0; q < 8; q++) {
                __nv_bfloat16 hv = __float2bfloat16(f[q]);
                wzr_h[(k + q) * 16 + j] = hv;
                wzr_l[(k + q) * 16 + j] = __float2bfloat16(f[q] - __bfloat162float(hv));
            }
            float4 w0 = *(const float4*)&Wch[(size_t)(n0c + j) * HH + k];
            float4 w1 = *(const float4*)&Wch[(size_t)(n0c + j) * HH + k + 4];
            float g[8] = {w0.x,w0.y,w0.z,w0.w,w1.x,w1.y,w1.z,w1.w};
#pragma unroll
            for (int q = 0; q < 8; q++) {
                __nv_bfloat16 hv = __float2bfloat16(g[q]);
                wc_h[(k + q) * 16 + j] = hv;
                wc_l[(k + q) * 16 + j] = __float2bfloat16(g[q] - __bfloat162float(hv));
            }
        }
    }

    // ---- init hidden ----
    for (int i = bid * 256 + tid; i < BH; i += NBLK * 256) g_h[i] = hidden[i];
    grid_barrier();

    // staging lane coords: lanes walk k (conflict-free 16B stores)
    const int rsub = lane >> 4;      // 0/1: row within warp pair
    const int kc   = lane & 15;      // 16B chunk along k

    for (int t = 0; t < TT; t++) {
        // =================== Phase A: z | r, C[64 x 16] ===================
        {
            const int wm = warp >> 1;            // m-tile 0..3
            const int ks = warp & 1;             // k half
            const int m0 = wm * 16;

            FragC c0, c1;
            wmma::fill_fragment(c0, 0.f);
            wmma::fill_fragment(c1, 0.f);

            float4 pf[8];
            // prologue: tile 0 -> regs -> buf0
#pragma unroll
            for (int p = 0; p < 4; p++) {
                int row = p * 16 + warp * 2 + rsub;
                const float* src = &g_h[(size_t)row * HH + kc * 8];
                pf[2*p]   = *(const float4*)&src[0];
                pf[2*p+1] = *(const float4*)&src[4];
            }
#pragma unroll
            for (int p = 0; p < 4; p++) {
                int row = p * 16 + warp * 2 + rsub;
                uint4 h4, l4; cvt8(pf[2*p], pf[2*p+1], &h4, &l4);
                *(uint4*)&hb[row * KPAD + kc * 8]        = h4;
                *(uint4*)&hb[HMAT + row * KPAD + kc * 8] = l4;
            }

            for (int kt = 0; kt < 8; kt++) {
                __syncthreads();
                if (kt < 7) {
#pragma unroll
                    for (int p = 0; p < 4; p++) {
                        int row = p * 16 + warp * 2 + rsub;
                        const float* src = &g_h[(size_t)row * HH + (kt+1) * 128 + kc * 8];
                        pf[2*p]   = *(const float4*)&src[0];
                        pf[2*p+1] = *(const float4*)&src[4];
                    }
                }
                const __nv_bfloat16* Hh = hb + (kt & 1) * 2 * HMAT;
                const __nv_bfloat16* Hl = Hh + HMAT;
#pragma unroll
                for (int s = 0; s < 4; s++) {
                    int kk = ks * 64 + s * 16;
                    int kg = kt * 128 + kk;
                    FragA ah, al; FragB bhf, blf;
                    wmma::load_matrix_sync(ah, Hh + m0 * KPAD + kk, KPAD);
                    wmma::load_matrix_sync(al, Hl + m0 * KPAD + kk, KPAD);
                    wmma::load_matrix_sync(bhf, wzr_h + kg * 16, 16);
                    wmma::load_matrix_sync(blf, wzr_l + kg * 16, 16);
                    wmma::mma_sync(c0, ah, bhf, c0);
                    wmma::mma_sync(c1, ah, blf, c1);
                    wmma::mma_sync(c1, al, bhf, c1);
                }
                if (kt < 7) {
                    __nv_bfloat16* Nh = hb + ((kt+1) & 1) * 2 * HMAT;
#pragma unroll
                    for (int p = 0; p < 4; p++) {
                        int row = p * 16 + warp * 2 + rsub;
                        uint4 h4, l4; cvt8(pf[2*p], pf[2*p+1], &h4, &l4);
                        *(uint4*)&Nh[row * KPAD + kc * 8]        = h4;
                        *(uint4*)&Nh[HMAT + row * KPAD + kc * 8] = l4;
                    }
                }
            }
#pragma unroll
            for (int i = 0; i < c0.num_elements; i++) c0.x[i] += c1.x[i];
            __syncthreads();   // all done reading buf1 / pbuf area free
            wmma::store_matrix_sync(pbuf + ks * 1024 + m0 * 16, c0, 16, wmma::mem_row_major);
            __syncthreads();

            // epilogue: sigmoid, write g_z or g_rh
            int b  = tid >> 2;
            int cg = (tid & 3) * 4;
            float4 s0 = *(const float4*)&pbuf[b * 16 + cg];
            float4 s1 = *(const float4*)&pbuf[1024 + b * 16 + cg];
            float s[4] = {s0.x + s1.x, s0.y + s1.y, s0.z + s1.z, s0.w + s1.w};
            int col = n0g + cg;
            if (gate == 0) {
                float4 xg = *(const float4*)&g_xz[(size_t)t * BH + b * HH + col];
                float4 r;
                r.x = 1.f / (1.f + __expf(-(s[0] + xg.x)));
                r.y = 1.f / (1.f + __expf(-(s[1] + xg.y)));
                r.z = 1.f / (1.f + __expf(-(s[2] + xg.z)));
                r.w = 1.f / (1.f + __expf(-(s[3] + xg.w)));
                *(float4*)&g_z[b * HH + col] = r;
            } else {
                float4 xg = *(const float4*)&g_xr[(size_t)t * BH + b * HH + col];
                float4 hv = *(const float4*)&g_h[b * HH + col];
                float4 r;
                r.x = hv.x / (1.f + __expf(-(s[0] + xg.x)));
                r.y = hv.y / (1.f + __expf(-(s[1] + xg.y)));
                r.z = hv.z / (1.f + __expf(-(s[2] + xg.z)));
                r.w = hv.w / (1.f + __expf(-(s[3] + xg.w)));
                *(float4*)&g_rh[b * HH + col] = r;
            }
        }
        grid_barrier();

        // =================== Phase B: candidate, C[32 x 16] ===================
        {
            const int ks = warp >> 1;            // k quarter 0..3
            const int wm = warp & 1;             // m-tile 0..1
            const int m0 = wm * 16;

            FragC c0, c1;
            wmma::fill_fragment(c0, 0.f);
            wmma::fill_fragment(c1, 0.f);

            float4 pf[4];
#pragma unroll
            for (int p = 0; p < 2; p++) {
                int row = p * 16 + warp * 2 + rsub;
                const float* src = &g_rh[(size_t)(bh * 32 + row) * HH + kc * 8];
                pf[2*p]   = *(const float4*)&src[0];
                pf[2*p+1] = *(const float4*)&src[4];
            }
#pragma unroll
            for (int p = 0; p < 2; p++) {
                int row = p * 16 + warp * 2 + rsub;
                uint4 h4, l4; cvt8(pf[2*p], pf[2*p+1], &h4, &l4);
                *(uint4*)&hb[row * KPAD + kc * 8]        = h4;
                *(uint4*)&hb[HMAT + row * KPAD + kc * 8] = l4;
            }

            for (int kt = 0; kt < 8; kt++) {
                __syncthreads();
                if (kt < 7) {
#pragma unroll
                    for (int p = 0; p < 2; p++) {
                        int row = p * 16 + warp * 2 + rsub;
                        const float* src = &g_rh[(size_t)(bh * 32 + row) * HH + (kt+1) * 128 + kc * 8];
                        pf[2*p]   = *(const float4*)&src[0];
                        pf[2*p+1] = *(const float4*)&src[4];
                    }
                }
                const __nv_bfloat16* Hh = hb + (kt & 1) * 2 * HMAT;
                const __nv_bfloat16* Hl = Hh + HMAT;
#pragma unroll
                for (int s = 0; s < 2; s++) {
                    int kk = ks * 32 + s * 16;
                    int kg = kt * 128 + kk;
                    FragA ah, al; FragB bhf, blf;
                    wmma::load_matrix_sync(ah, Hh + m0 * KPAD + kk, KPAD);
                    wmma::load_matrix_sync(al, Hl + m0 * KPAD + kk, KPAD);
                    wmma::load_matrix_sync(bhf, wc_h + kg * 16, 16);
                    wmma::load_matrix_sync(blf, wc_l + kg * 16, 16);
                    wmma::mma_sync(c0, ah, bhf, c0);
                    wmma::mma_sync(c1, ah, blf, c1);
                    wmma::mma_sync(c1, al, bhf, c1);
                }
                if (kt < 7) {
                    __nv_bfloat16* Nh = hb + ((kt+1) & 1) * 2 * HMAT;
#pragma unroll
                    for (int p = 0; p < 2; p++) {
                        int row = p * 16 + warp * 2 + rsub;
                        uint4 h4, l4; cvt8(pf[2*p], pf[2*p+1], &h4, &l4);
                        *(uint4*)&Nh[row * KPAD + kc * 8]        = h4;
                        *(uint4*)&Nh[HMAT + row * KPAD + kc * 8] = l4;
                    }
                }
            }
#pragma unroll
            for (int i = 0; i < c0.num_elements; i++) c0.x[i] += c1.x[i];
            __syncthreads();
            wmma::store_matrix_sync(pbuf + ks * 512 + m0 * 16, c0, 16, wmma::mem_row_major);
            __syncthreads();

            // epilogue: tanh + blend, 2 elems/thread
            int row = tid >> 3;
            int c0i = (tid & 7) * 2;
            float s0 = 0.f, s1 = 0.f;
#pragma unroll
            for (int q = 0; q < 4; q++) {
                s0 += pbuf[q * 512 + row * 16 + c0i + 0];
                s1 += pbuf[q * 512 + row * 16 + c0i + 1];
            }
            int b   = bh * 32 + row;
            int col = n0c + c0i;
            size_t base = (size_t)t * BH + b * HH + col;
            int idx = b * HH + col;
            float xc0 = g_xc[base + 0], xc1 = g_xc[base + 1];
            float z0  = g_z[idx + 0],   z1  = g_z[idx + 1];
            float h0  = g_h[idx + 0],   h1  = g_h[idx + 1];
            float cc0 = tanhf(s0 + xc0);
            float cc1 = tanhf(s1 + xc1);
            float hn0 = (1.f - z0) * h0 + z0 * cc0;
            float hn1 = (1.f - z1) * h1 + z1 * cc1;
            g_h[idx + 0] = hn0; g_h[idx + 1] = hn1;
            out[base + 0] = hn0; out[base + 1] = hn1;
            if (t == TT - 1) {
                out[(size_t)TT * BH + idx + 0] = hn0;
                out[(size_t)TT * BH + idx + 1] = hn1;
            }
        }
        grid_barrier();
    }
}

// ---------------- launch ----------------
extern "C" void kernel_launch(void* const* d_in, const int* in_sizes, int n_in,
                              void* d_out, int out_size)
{
    const float* x      = (const float*)d_in[0];
    const float* hidden = (const float*)d_in[1];
    const float* Wzi = (const float*)d_in[2];  const float* bzi = (const float*)d_in[3];
    const float* Wzh = (const float*)d_in[4];  const float* bzh = (const float*)d_in[5];
    const float* Wri = (const float*)d_in[6];  const float* bri = (const float*)d_in[7];
    const float* Wrh = (const float*)d_in[8];  const float* brh = (const float*)d_in[9];
    const float* Wci = (const float*)d_in[10]; const float* bci = (const float*)d_in[11];
    const float* Wch = (const float*)d_in[12]; const float* bch = (const float*)d_in[13];
    float* out = (float*)d_out;

    dim3 gp(HH / BN, (TT * BB) / BM, 3);
    gru_input_proj<<<gp, 256>>>(x, Wzi, bzi, bzh, Wri, bri, brh, Wci, bci, bch);

    cudaFuncSetAttribute(gru_recurrence,
                         cudaFuncAttributeMaxDynamicSharedMemorySize, SMEM_BYTES);
    gru_recurrence<<<NBLK, 256, SMEM_BYTES>>>(hidden, Wzh, Wrh, Wch, out);
}

// round 6
// speedup vs baseline: 2.0374x; 1.0144x over previous
#include <cuda_runtime.h>
#include <cuda_bf16.h>
#include <mma.h>
#include <math.h>

using namespace nvcuda;

#define TT 512
#define BB 64
#define II 1024
#define HH 1024
#define BH (BB*HH)          // 65536
#define NBLK 128            // persistent grid, 1 block/SM

// ---------------- device scratch ----------------
__device__ float g_xz[(size_t)TT*BH];
__device__ float g_xr[(size_t)TT*BH];
__device__ float g_xc[(size_t)TT*BH];
__device__ float g_h[BH];
__device__ float g_z[BH];
__device__ float g_rh[BH];

// monotonic grid barrier (validated R2/R3)
__device__ unsigned long long g_arrive = 0;
__device__ volatile unsigned long long g_release = 0;

__device__ __forceinline__ void grid_barrier() {
    __syncthreads();
    if (threadIdx.x == 0) {
        __threadfence();
        unsigned long long tok = atomicAdd(&g_arrive, 1ULL);
        unsigned long long gen = tok / NBLK;
        if ((tok % NBLK) == (NBLK - 1)) {
            g_release = gen + 1;
        } else {
            while (g_release < gen + 1) { }
        }
        __threadfence();
    }
    __syncthreads();
}

// ---------------- input projections (validated R2/R3) ----------------
#define BM 128
#define BN 128
#define BK 16

__global__ __launch_bounds__(256, 2)
void gru_input_proj(const float* __restrict__ x,
                    const float* __restrict__ Wzi, const float* __restrict__ bzi, const float* __restrict__ bzh,
                    const float* __restrict__ Wri, const float* __restrict__ bri, const float* __restrict__ brh,
                    const float* __restrict__ Wci, const float* __restrict__ bci, const float* __restrict__ bch)
{
    const int gate = blockIdx.z;
    const float* W; const float* b1; const float* b2; float* out;
    if (gate == 0)      { W = Wzi; b1 = bzi; b2 = bzh; out = g_xz; }
    else if (gate == 1) { W = Wri; b1 = bri; b2 = brh; out = g_xr; }
    else                { W = Wci; b1 = bci; b2 = bch; out = g_xc; }

    __shared__ float As[BK][BM];
    __shared__ float Bs[BK][BN];

    const int m0 = blockIdx.y * BM;
    const int n0 = blockIdx.x * BN;
    const int tid = threadIdx.x;
    const int tx = tid & 15;
    const int ty = tid >> 4;

    float acc[8][8];
#pragma unroll
    for (int i = 0; i < 8; i++)
#pragma unroll
        for (int j = 0; j < 8; j++) acc[i][j] = 0.f;

    for (int k0 = 0; k0 < II; k0 += BK) {
#pragma unroll
        for (int i = 0; i < 2; i++) {
            int slot = tid + i * 256;
            int r  = slot >> 2;
            int kq = (slot & 3) << 2;
            float4 va = *(const float4*)&x[(size_t)(m0 + r) * II + k0 + kq];
            As[kq + 0][r] = va.x; As[kq + 1][r] = va.y; As[kq + 2][r] = va.z; As[kq + 3][r] = va.w;
            float4 vb = *(const float4*)&W[(size_t)(n0 + r) * II + k0 + kq];
            Bs[kq + 0][r] = vb.x; Bs[kq + 1][r] = vb.y; Bs[kq + 2][r] = vb.z; Bs[kq + 3][r] = vb.w;
        }
        __syncthreads();

#pragma unroll
        for (int kk = 0; kk < BK; kk++) {
            float a[8], b[8];
            float4 a0 = *(const float4*)&As[kk][ty * 8];
            float4 a1 = *(const float4*)&As[kk][ty * 8 + 4];
            float4 b0 = *(const float4*)&Bs[kk][tx * 8];
            float4 b1v = *(const float4*)&Bs[kk][tx * 8 + 4];
            a[0]=a0.x;a[1]=a0.y;a[2]=a0.z;a[3]=a0.w;a[4]=a1.x;a[5]=a1.y;a[6]=a1.z;a[7]=a1.w;
            b[0]=b0.x;b[1]=b0.y;b[2]=b0.z;b[3]=b0.w;b[4]=b1v.x;b[5]=b1v.y;b[6]=b1v.z;b[7]=b1v.w;
#pragma unroll
            for (int i = 0; i < 8; i++)
#pragma unroll
                for (int j = 0; j < 8; j++)
                    acc[i][j] += a[i] * b[j];
        }
        __syncthreads();
    }

    float bb[8];
#pragma unroll
    for (int j = 0; j < 8; j++) {
        int n = n0 + tx * 8 + j;
        bb[j] = b1[n] + b2[n];
    }
#pragma unroll
    for (int i = 0; i < 8; i++) {
        int m = m0 + ty * 8 + i;
#pragma unroll
        for (int jq = 0; jq < 2; jq++) {
            float4 v;
            v.x = acc[i][jq * 4 + 0] + bb[jq * 4 + 0];
            v.y = acc[i][jq * 4 + 1] + bb[jq * 4 + 1];
            v.z = acc[i][jq * 4 + 2] + bb[jq * 4 + 2];
            v.w = acc[i][jq * 4 + 3] + bb[jq * 4 + 3];
            *(float4*)&out[(size_t)m * HH + n0 + tx * 8 + jq * 4] = v;
        }
    }
}

// ---------------- tensor-core persistent recurrence ----------------
// bf16 split (hi/lo) wmma m16n16k16, fp32 accumulate, 3 mma passes.
// smem (bytes):
//   wzr_hi/lo : 2 x 1024x16 bf16 = 65536
//   wc_hi/lo  : 2 x 1024x16 bf16 = 65536
//   hbuf      : 2 buffers x (hi+lo) x [64][KPAD] bf16 = 69632
//   pbuf (fp32 partials, 8KB) aliases hbuf buffer 0
#define KPAD 136
#define HMAT (64*KPAD)                 // bf16 elems per matrix
#define SMEM_BYTES (65536 + 65536 + 2*2*HMAT*2)

typedef wmma::fragment<wmma::matrix_a, 16, 16, 16, __nv_bfloat16, wmma::row_major> FragA;
typedef wmma::fragment<wmma::matrix_b, 16, 16, 16, __nv_bfloat16, wmma::row_major> FragB;
typedef wmma::fragment<wmma::accumulator, 16, 16, 16, float> FragC;

// convert 8 fp32 -> 8 bf16 hi + 8 bf16 lo packed as uint4
__device__ __forceinline__ void cvt8(float4 a, float4 b, uint4* hi4, uint4* lo4)
{
    union { __nv_bfloat16 h[8]; uint4 u; } H, L;
    float f[8] = {a.x, a.y, a.z, a.w, b.x, b.y, b.z, b.w};
#pragma unroll
    for (int j = 0; j < 8; j++) {
        __nv_bfloat16 hv = __float2bfloat16(f[j]);
        H.h[j] = hv;
        L.h[j] = __float2bfloat16(f[j] - __bfloat162float(hv));
    }
    *hi4 = H.u; *lo4 = L.u;
}

__global__ __launch_bounds__(256, 1)
void gru_recurrence(const float* __restrict__ hidden,
                    const float* __restrict__ Wzh,
                    const float* __restrict__ Wrh,
                    const float* __restrict__ Wch,
                    float* __restrict__ out)
{
    extern __shared__ char smem[];
    __nv_bfloat16* wzr_h = (__nv_bfloat16*)smem;
    __nv_bfloat16* wzr_l = wzr_h + 1024 * 16;
    __nv_bfloat16* wc_h  = wzr_l + 1024 * 16;
    __nv_bfloat16* wc_l  = wc_h  + 1024 * 16;
    __nv_bfloat16* hb    = wc_l  + 1024 * 16;   // 2 x (hi, lo) [64][KPAD]
    float* pbuf = (float*)hb;                    // aliases buffer 0

    const int tid  = threadIdx.x;
    const int bid  = blockIdx.x;
    const int warp = tid >> 5;
    const int lane = tid & 31;

    const int gate = bid >> 6;                   // phase A: 0=z, 1=r
    const int n0g  = (bid & 63) * 16;            // phase A col base (within gate)
    const int n0c  = (bid & 63) * 16;            // phase B col base
    const int bh   = bid >> 6;                   // phase B batch half

    // ---- one-time: convert this block's weight slices to bf16 hi/lo in smem ----
    {
        const float* WA = gate ? Wrh : Wzh;
        int j  = tid >> 4;        // 0..15 col
        int kc = tid & 15;        // k chunk
#pragma unroll
        for (int i = 0; i < 8; i++) {
            int k = i * 128 + kc * 8;
            float4 v0 = *(const float4*)&WA[(size_t)(n0g + j) * HH + k];
            float4 v1 = *(const float4*)&WA[(size_t)(n0g + j) * HH + k + 4];
            float f[8] = {v0.x,v0.y,v0.z,v0.w,v1.x,v1.y,v1.z,v1.w};
#pragma unroll
            for (int q = 0; q < 8; q++) {
                __nv_bfloat16 hv = __float2bfloat16(f[q]);
                wzr_h[(k + q) * 16 + j] = hv;
                wzr_l[(k + q) * 16 + j] = __float2bfloat16(f[q] - __bfloat162float(hv));
            }
            float4 w0 = *(const float4*)&Wch[(size_t)(n0c + j) * HH + k];
            float4 w1 = *(const float4*)&Wch[(size_t)(n0c + j) * HH + k + 4];
            float g[8] = {w0.x,w0.y,w0.z,w0.w,w1.x,w1.y,w1.z,w1.w};
#pragma unroll
            for (int q = 0; q < 8; q++) {
                __nv_bfloat16 hv = __float2bfloat16(g[q]);
                wc_h[(k + q) * 16 + j] = hv;
                wc_l[(k + q) * 16 + j] = __float2bfloat16(g[q] - __bfloat162float(hv));
            }
        }
    }

    // ---- init hidden ----
    for (int i = bid * 256 + tid; i < BH; i += NBLK * 256) g_h[i] = hidden[i];
    grid_barrier();

    // staging lane coords: lanes walk k (conflict-free 16B stores)
    const int rsub = lane >> 4;      // 0/1: row within warp pair
    const int kc   = lane & 15;      // 16B chunk along k

    for (int t = 0; t < TT; t++) {
        // =================== Phase A: z | r, C[64 x 16] ===================
        {
            const int wm = warp >> 1;            // m-tile 0..3
            const int ks = warp & 1;             // k half
            const int m0 = wm * 16;

            FragC c0, c1;
            wmma::fill_fragment(c0, 0.f);
            wmma::fill_fragment(c1, 0.f);

            float4 pf[8];
            // prologue: tile 0 -> regs -> buf0
#pragma unroll
            for (int p = 0; p < 4; p++) {
                int row = p * 16 + warp * 2 + rsub;
                const float* src = &g_h[(size_t)row * HH + kc * 8];
                pf[2*p]   = *(const float4*)&src[0];
                pf[2*p+1] = *(const float4*)&src[4];
            }
#pragma unroll
            for (int p = 0; p < 4; p++) {
                int row = p * 16 + warp * 2 + rsub;
                uint4 h4, l4; cvt8(pf[2*p], pf[2*p+1], &h4, &l4);
                *(uint4*)&hb[row * KPAD + kc * 8]        = h4;
                *(uint4*)&hb[HMAT + row * KPAD + kc * 8] = l4;
            }

            for (int kt = 0; kt < 8; kt++) {
                __syncthreads();
                if (kt < 7) {
#pragma unroll
                    for (int p = 0; p < 4; p++) {
                        int row = p * 16 + warp * 2 + rsub;
                        const float* src = &g_h[(size_t)row * HH + (kt+1) * 128 + kc * 8];
                        pf[2*p]   = *(const float4*)&src[0];
                        pf[2*p+1] = *(const float4*)&src[4];
                    }
                }
                const __nv_bfloat16* Hh = hb + (kt & 1) * 2 * HMAT;
                const __nv_bfloat16* Hl = Hh + HMAT;
#pragma unroll
                for (int s = 0; s < 4; s++) {
                    int kk = ks * 64 + s * 16;
                    int kg = kt * 128 + kk;
                    FragA ah, al; FragB bhf, blf;
                    wmma::load_matrix_sync(ah, Hh + m0 * KPAD + kk, KPAD);
                    wmma::load_matrix_sync(al, Hl + m0 * KPAD + kk, KPAD);
                    wmma::load_matrix_sync(bhf, wzr_h + kg * 16, 16);
                    wmma::load_matrix_sync(blf, wzr_l + kg * 16, 16);
                    wmma::mma_sync(c0, ah, bhf, c0);
                    wmma::mma_sync(c1, ah, blf, c1);
                    wmma::mma_sync(c1, al, bhf, c1);
                }
                if (kt < 7) {
                    __nv_bfloat16* Nh = hb + ((kt+1) & 1) * 2 * HMAT;
#pragma unroll
                    for (int p = 0; p < 4; p++) {
                        int row = p * 16 + warp * 2 + rsub;
                        uint4 h4, l4; cvt8(pf[2*p], pf[2*p+1], &h4, &l4);
                        *(uint4*)&Nh[row * KPAD + kc * 8]        = h4;
                        *(uint4*)&Nh[HMAT + row * KPAD + kc * 8] = l4;
                    }
                }
            }
#pragma unroll
            for (int i = 0; i < c0.num_elements; i++) c0.x[i] += c1.x[i];
            __syncthreads();   // all done reading buf1 / pbuf area free
            wmma::store_matrix_sync(pbuf + ks * 1024 + m0 * 16, c0, 16, wmma::mem_row_major);
            __syncthreads();

            // epilogue: sigmoid, write g_z or g_rh
            int b  = tid >> 2;
            int cg = (tid & 3) * 4;
            float4 s0 = *(const float4*)&pbuf[b * 16 + cg];
            float4 s1 = *(const float4*)&pbuf[1024 + b * 16 + cg];
            float s[4] = {s0.x + s1.x, s0.y + s1.y, s0.z + s1.z, s0.w + s1.w};
            int col = n0g + cg;
            if (gate == 0) {
                float4 xg = *(const float4*)&g_xz[(size_t)t * BH + b * HH + col];
                float4 r;
                r.x = 1.f / (1.f + __expf(-(s[0] + xg.x)));
                r.y = 1.f / (1.f + __expf(-(s[1] + xg.y)));
                r.z = 1.f / (1.f + __expf(-(s[2] + xg.z)));
                r.w = 1.f / (1.f + __expf(-(s[3] + xg.w)));
                *(float4*)&g_z[b * HH + col] = r;
            } else {
                float4 xg = *(const float4*)&g_xr[(size_t)t * BH + b * HH + col];
                float4 hv = *(const float4*)&g_h[b * HH + col];
                float4 r;
                r.x = hv.x / (1.f + __expf(-(s[0] + xg.x)));
                r.y = hv.y / (1.f + __expf(-(s[1] + xg.y)));
                r.z = hv.z / (1.f + __expf(-(s[2] + xg.z)));
                r.w = hv.w / (1.f + __expf(-(s[3] + xg.w)));
                *(float4*)&g_rh[b * HH + col] = r;
            }
        }
        grid_barrier();

        // =================== Phase B: candidate, C[32 x 16] ===================
        {
            const int ks = warp >> 1;            // k quarter 0..3
            const int wm = warp & 1;             // m-tile 0..1
            const int m0 = wm * 16;

            FragC c0, c1;
            wmma::fill_fragment(c0, 0.f);
            wmma::fill_fragment(c1, 0.f);

            float4 pf[4];
#pragma unroll
            for (int p = 0; p < 2; p++) {
                int row = p * 16 + warp * 2 + rsub;
                const float* src = &g_rh[(size_t)(bh * 32 + row) * HH + kc * 8];
                pf[2*p]   = *(const float4*)&src[0];
                pf[2*p+1] = *(const float4*)&src[4];
            }
#pragma unroll
            for (int p = 0; p < 2; p++) {
                int row = p * 16 + warp * 2 + rsub;
                uint4 h4, l4; cvt8(pf[2*p], pf[2*p+1], &h4, &l4);
                *(uint4*)&hb[row * KPAD + kc * 8]        = h4;
                *(uint4*)&hb[HMAT + row * KPAD + kc * 8] = l4;
            }

            for (int kt = 0; kt < 8; kt++) {
                __syncthreads();
                if (kt < 7) {
#pragma unroll
                    for (int p = 0; p < 2; p++) {
                        int row = p * 16 + warp * 2 + rsub;
                        const float* src = &g_rh[(size_t)(bh * 32 + row) * HH + (kt+1) * 128 + kc * 8];
                        pf[2*p]   = *(const float4*)&src[0];
                        pf[2*p+1] = *(const float4*)&src[4];
                    }
                }
                const __nv_bfloat16* Hh = hb + (kt & 1) * 2 * HMAT;
                const __nv_bfloat16* Hl = Hh + HMAT;
#pragma unroll
                for (int s = 0; s < 2; s++) {
                    int kk = ks * 32 + s * 16;
                    int kg = kt * 128 + kk;
                    FragA ah, al; FragB bhf, blf;
                    wmma::load_matrix_sync(ah, Hh + m0 * KPAD + kk, KPAD);
                    wmma::load_matrix_sync(al, Hl + m0 * KPAD + kk, KPAD);
                    wmma::load_matrix_sync(bhf, wc_h + kg * 16, 16);
                    wmma::load_matrix_sync(blf, wc_l + kg * 16, 16);
                    wmma::mma_sync(c0, ah, bhf, c0);
                    wmma::mma_sync(c1, ah, blf, c1);
                    wmma::mma_sync(c1, al, bhf, c1);
                }
                if (kt < 7) {
                    __nv_bfloat16* Nh = hb + ((kt+1) & 1) * 2 * HMAT;
#pragma unroll
                    for (int p = 0; p < 2; p++) {
                        int row = p * 16 + warp * 2 + rsub;
                        uint4 h4, l4; cvt8(pf[2*p], pf[2*p+1], &h4, &l4);
                        *(uint4*)&Nh[row * KPAD + kc * 8]        = h4;
                        *(uint4*)&Nh[HMAT + row * KPAD + kc * 8] = l4;
                    }
                }
            }
#pragma unroll
            for (int i = 0; i < c0.num_elements; i++) c0.x[i] += c1.x[i];
            __syncthreads();
            wmma::store_matrix_sync(pbuf + ks * 512 + m0 * 16, c0, 16, wmma::mem_row_major);
            __syncthreads();

            // epilogue: tanh + blend, 2 elems/thread
            int row = tid >> 3;
            int c0i = (tid & 7) * 2;
            float s0 = 0.f, s1 = 0.f;
#pragma unroll
            for (int q = 0; q < 4; q++) {
                s0 += pbuf[q * 512 + row * 16 + c0i + 0];
                s1 += pbuf[q * 512 + row * 16 + c0i + 1];
            }
            int b   = bh * 32 + row;
            int col = n0c + c0i;
            size_t base = (size_t)t * BH + b * HH + col;
            int idx = b * HH + col;
            float xc0 = g_xc[base + 0], xc1 = g_xc[base + 1];
            float z0  = g_z[idx + 0],   z1  = g_z[idx + 1];
            float h0  = g_h[idx + 0],   h1  = g_h[idx + 1];
            float cc0 = tanhf(s0 + xc0);
            float cc1 = tanhf(s1 + xc1);
            float hn0 = (1.f - z0) * h0 + z0 * cc0;
            float hn1 = (1.f - z1) * h1 + z1 * cc1;
            g_h[idx + 0] = hn0; g_h[idx + 1] = hn1;
            out[base + 0] = hn0; out[base + 1] = hn1;
            if (t == TT - 1) {
                out[(size_t)TT * BH + idx + 0] = hn0;
                out[(size_t)TT * BH + idx + 1] = hn1;
            }
        }
        grid_barrier();
    }
}

// ---------------- launch ----------------
extern "C" void kernel_launch(void* const* d_in, const int* in_sizes, int n_in,
                              void* d_out, int out_size)
{
    const float* x      = (const float*)d_in[0];
    const float* hidden = (const float*)d_in[1];
    const float* Wzi = (const float*)d_in[2];  const float* bzi = (const float*)d_in[3];
    const float* Wzh = (const float*)d_in[4];  const float* bzh = (const float*)d_in[5];
    const float* Wri = (const float*)d_in[6];  const float* bri = (const float*)d_in[7];
    const float* Wrh = (const float*)d_in[8];  const float* brh = (const float*)d_in[9];
    const float* Wci = (const float*)d_in[10]; const float* bci = (const float*)d_in[11];
    const float* Wch = (const float*)d_in[12]; const float* bch = (const float*)d_in[13];
    float* out = (float*)d_out;

    dim3 gp(HH / BN, (TT * BB) / BM, 3);
    gru_input_proj<<<gp, 256>>>(x, Wzi, bzi, bzh, Wri, bri, brh, Wci, bci, bch);

    cudaFuncSetAttribute(gru_recurrence,
                         cudaFuncAttributeMaxDynamicSharedMemorySize, SMEM_BYTES);
    gru_recurrence<<<NBLK, 256, SMEM_BYTES>>>(hidden, Wzh, Wrh, Wch, out);
}

// round 7
// speedup vs baseline: 2.2330x; 1.0960x over previous
#include <cuda_runtime.h>
#include <cuda_bf16.h>
#include <mma.h>
#include <math.h>

using namespace nvcuda;

#define TT 512
#define BB 64
#define II 1024
#define HH 1024
#define BH (BB*HH)          // 65536
#define NBLK 128            // persistent grid, 1 block/SM

// ---------------- device scratch ----------------
__device__ float g_xz[(size_t)TT*BH];
__device__ float g_xr[(size_t)TT*BH];
__device__ float g_xc[(size_t)TT*BH];
__device__ float g_h[BH];                 // fp32 hidden (blend / r*h)
__device__ float g_z[BH];                 // update gate
__device__ __nv_bfloat16 g_h_hi[BH];      // bf16 split mirrors of h
__device__ __nv_bfloat16 g_h_lo[BH];
__device__ __nv_bfloat16 g_rh_hi[BH];     // bf16 split of r*h
__device__ __nv_bfloat16 g_rh_lo[BH];

// monotonic grid barrier (validated R2-R6)
__device__ unsigned long long g_arrive = 0;
__device__ volatile unsigned long long g_release = 0;

__device__ __forceinline__ void grid_barrier() {
    __syncthreads();
    if (threadIdx.x == 0) {
        __threadfence();
        unsigned long long tok = atomicAdd(&g_arrive, 1ULL);
        unsigned long long gen = tok / NBLK;
        if ((tok % NBLK) == (NBLK - 1)) {
            g_release = gen + 1;
        } else {
            while (g_release < gen + 1) { }
        }
        __threadfence();
    }
    __syncthreads();
}

// ---------------- input projections (validated R2+) ----------------
#define BM 128
#define BN 128
#define BK 16

__global__ __launch_bounds__(256, 2)
void gru_input_proj(const float* __restrict__ x,
                    const float* __restrict__ Wzi, const float* __restrict__ bzi, const float* __restrict__ bzh,
                    const float* __restrict__ Wri, const float* __restrict__ bri, const float* __restrict__ brh,
                    const float* __restrict__ Wci, const float* __restrict__ bci, const float* __restrict__ bch)
{
    const int gate = blockIdx.z;
    const float* W; const float* b1; const float* b2; float* out;
    if (gate == 0)      { W = Wzi; b1 = bzi; b2 = bzh; out = g_xz; }
    else if (gate == 1) { W = Wri; b1 = bri; b2 = brh; out = g_xr; }
    else                { W = Wci; b1 = bci; b2 = bch; out = g_xc; }

    __shared__ float As[BK][BM];
    __shared__ float Bs[BK][BN];

    const int m0 = blockIdx.y * BM;
    const int n0 = blockIdx.x * BN;
    const int tid = threadIdx.x;
    const int tx = tid & 15;
    const int ty = tid >> 4;

    float acc[8][8];
#pragma unroll
    for (int i = 0; i < 8; i++)
#pragma unroll
        for (int j = 0; j < 8; j++) acc[i][j] = 0.f;

    for (int k0 = 0; k0 < II; k0 += BK) {
#pragma unroll
        for (int i = 0; i < 2; i++) {
            int slot = tid + i * 256;
            int r  = slot >> 2;
            int kq = (slot & 3) << 2;
            float4 va = *(const float4*)&x[(size_t)(m0 + r) * II + k0 + kq];
            As[kq + 0][r] = va.x; As[kq + 1][r] = va.y; As[kq + 2][r] = va.z; As[kq + 3][r] = va.w;
            float4 vb = *(const float4*)&W[(size_t)(n0 + r) * II + k0 + kq];
            Bs[kq + 0][r] = vb.x; Bs[kq + 1][r] = vb.y; Bs[kq + 2][r] = vb.z; Bs[kq + 3][r] = vb.w;
        }
        __syncthreads();

#pragma unroll
        for (int kk = 0; kk < BK; kk++) {
            float a[8], b[8];
            float4 a0 = *(const float4*)&As[kk][ty * 8];
            float4 a1 = *(const float4*)&As[kk][ty * 8 + 4];
            float4 b0 = *(const float4*)&Bs[kk][tx * 8];
            float4 b1v = *(const float4*)&Bs[kk][tx * 8 + 4];
            a[0]=a0.x;a[1]=a0.y;a[2]=a0.z;a[3]=a0.w;a[4]=a1.x;a[5]=a1.y;a[6]=a1.z;a[7]=a1.w;
            b[0]=b0.x;b[1]=b0.y;b[2]=b0.z;b[3]=b0.w;b[4]=b1v.x;b[5]=b1v.y;b[6]=b1v.z;b[7]=b1v.w;
#pragma unroll
            for (int i = 0; i < 8; i++)
#pragma unroll
                for (int j = 0; j < 8; j++)
                    acc[i][j] += a[i] * b[j];
        }
        __syncthreads();
    }

    float bb[8];
#pragma unroll
    for (int j = 0; j < 8; j++) {
        int n = n0 + tx * 8 + j;
        bb[j] = b1[n] + b2[n];
    }
#pragma unroll
    for (int i = 0; i < 8; i++) {
        int m = m0 + ty * 8 + i;
#pragma unroll
        for (int jq = 0; jq < 2; jq++) {
            float4 v;
            v.x = acc[i][jq * 4 + 0] + bb[jq * 4 + 0];
            v.y = acc[i][jq * 4 + 1] + bb[jq * 4 + 1];
            v.z = acc[i][jq * 4 + 2] + bb[jq * 4 + 2];
            v.w = acc[i][jq * 4 + 3] + bb[jq * 4 + 3];
            *(float4*)&out[(size_t)m * HH + n0 + tx * 8 + jq * 4] = v;
        }
    }
}

// ---------------- tensor-core persistent recurrence ----------------
// bf16 split wmma, fp32 acc, 3 independent mma chains.
// h/rh kept as global bf16 hi/lo mirrors -> staging loads bf16 directly,
// no per-step conversions, half the L2 bytes.
#define KPAD 136
#define HMAT (64*KPAD)
#define SMEM_BYTES (4*1024*16*2 + 2*2*HMAT*2)   // 131072 + 69632 = 200704

typedef wmma::fragment<wmma::matrix_a, 16, 16, 16, __nv_bfloat16, wmma::row_major> FragA;
typedef wmma::fragment<wmma::matrix_b, 16, 16, 16, __nv_bfloat16, wmma::row_major> FragB;
typedef wmma::fragment<wmma::accumulator, 16, 16, 16, float> FragC;

__global__ __launch_bounds__(256, 1)
void gru_recurrence(const float* __restrict__ hidden,
                    const float* __restrict__ Wzh,
                    const float* __restrict__ Wrh,
                    const float* __restrict__ Wch,
                    float* __restrict__ out)
{
    extern __shared__ char smem[];
    __nv_bfloat16* wzr_h = (__nv_bfloat16*)smem;
    __nv_bfloat16* wzr_l = wzr_h + 1024 * 16;
    __nv_bfloat16* wc_h  = wzr_l + 1024 * 16;
    __nv_bfloat16* wc_l  = wc_h  + 1024 * 16;
    __nv_bfloat16* hb    = wc_l  + 1024 * 16;   // 2 bufs x (hi, lo) [64][KPAD]
    float* pbuf = (float*)hb;                    // aliases buffer 0

    const int tid  = threadIdx.x;
    const int bid  = blockIdx.x;
    const int warp = tid >> 5;
    const int lane = tid & 31;

    const int gate = bid >> 6;                   // phase A: 0=z, 1=r
    const int n0g  = (bid & 63) * 16;
    const int n0c  = (bid & 63) * 16;
    const int bh   = bid >> 6;                   // phase B batch half

    // ---- one-time: weight slices -> bf16 hi/lo in smem ----
    {
        const float* WA = gate ? Wrh : Wzh;
        int j  = tid >> 4;
        int kc4 = tid & 15;
#pragma unroll
        for (int i = 0; i < 8; i++) {
            int k = i * 128 + kc4 * 8;
            float4 v0 = *(const float4*)&WA[(size_t)(n0g + j) * HH + k];
            float4 v1 = *(const float4*)&WA[(size_t)(n0g + j) * HH + k + 4];
            float f[8] = {v0.x,v0.y,v0.z,v0.w,v1.x,v1.y,v1.z,v1.w};
#pragma unroll
            for (int q = 0; q < 8; q++) {
                __nv_bfloat16 hv = __float2bfloat16(f[q]);
                wzr_h[(k + q) * 16 + j] = hv;
                wzr_l[(k + q) * 16 + j] = __float2bfloat16(f[q] - __bfloat162float(hv));
            }
            float4 w0 = *(const float4*)&Wch[(size_t)(n0c + j) * HH + k];
            float4 w1 = *(const float4*)&Wch[(size_t)(n0c + j) * HH + k + 4];
            float g[8] = {w0.x,w0.y,w0.z,w0.w,w1.x,w1.y,w1.z,w1.w};
#pragma unroll
            for (int q = 0; q < 8; q++) {
                __nv_bfloat16 hv = __float2bfloat16(g[q]);
                wc_h[(k + q) * 16 + j] = hv;
                wc_l[(k + q) * 16 + j] = __float2bfloat16(g[q] - __bfloat162float(hv));
            }
        }
    }

    // ---- init hidden (fp32 + bf16 mirrors) ----
    for (int i = bid * 256 + tid; i < BH; i += NBLK * 256) {
        float v = hidden[i];
        g_h[i] = v;
        __nv_bfloat16 hv = __float2bfloat16(v);
        g_h_hi[i] = hv;
        g_h_lo[i] = __float2bfloat16(v - __bfloat162float(hv));
    }
    grid_barrier();

    const int rsub = lane >> 4;      // 0/1
    const int kc   = lane & 15;      // 16B chunk along k (8 bf16)

    for (int t = 0; t < TT; t++) {
        // =================== Phase A: z | r, C[64 x 16] ===================
        {
            const int wm = warp >> 1;
            const int ks = warp & 1;
            const int m0 = wm * 16;

            FragC c0, c1, c2;
            wmma::fill_fragment(c0, 0.f);
            wmma::fill_fragment(c1, 0.f);
            wmma::fill_fragment(c2, 0.f);

            uint4 pf[8];
#pragma unroll
            for (int p = 0; p < 4; p++) {
                int row = p * 16 + warp * 2 + rsub;
                pf[2*p]   = *(const uint4*)&g_h_hi[(size_t)row * HH + kc * 8];
                pf[2*p+1] = *(const uint4*)&g_h_lo[(size_t)row * HH + kc * 8];
            }
#pragma unroll
            for (int p = 0; p < 4; p++) {
                int row = p * 16 + warp * 2 + rsub;
                *(uint4*)&hb[row * KPAD + kc * 8]        = pf[2*p];
                *(uint4*)&hb[HMAT + row * KPAD + kc * 8] = pf[2*p+1];
            }

            for (int kt = 0; kt < 8; kt++) {
                __syncthreads();
                if (kt < 7) {
#pragma unroll
                    for (int p = 0; p < 4; p++) {
                        int row = p * 16 + warp * 2 + rsub;
                        size_t off = (size_t)row * HH + (kt+1) * 128 + kc * 8;
                        pf[2*p]   = *(const uint4*)&g_h_hi[off];
                        pf[2*p+1] = *(const uint4*)&g_h_lo[off];
                    }
                }
                const __nv_bfloat16* Hh = hb + (kt & 1) * 2 * HMAT;
                const __nv_bfloat16* Hl = Hh + HMAT;
#pragma unroll
                for (int s = 0; s < 4; s++) {
                    int kk = ks * 64 + s * 16;
                    int kg = kt * 128 + kk;
                    FragA ah, al; FragB bhf, blf;
                    wmma::load_matrix_sync(ah, Hh + m0 * KPAD + kk, KPAD);
                    wmma::load_matrix_sync(al, Hl + m0 * KPAD + kk, KPAD);
                    wmma::load_matrix_sync(bhf, wzr_h + kg * 16, 16);
                    wmma::load_matrix_sync(blf, wzr_l + kg * 16, 16);
                    wmma::mma_sync(c0, ah, bhf, c0);
                    wmma::mma_sync(c1, ah, blf, c1);
                    wmma::mma_sync(c2, al, bhf, c2);
                }
                if (kt < 7) {
                    __nv_bfloat16* Nh = hb + ((kt+1) & 1) * 2 * HMAT;
#pragma unroll
                    for (int p = 0; p < 4; p++) {
                        int row = p * 16 + warp * 2 + rsub;
                        *(uint4*)&Nh[row * KPAD + kc * 8]        = pf[2*p];
                        *(uint4*)&Nh[HMAT + row * KPAD + kc * 8] = pf[2*p+1];
                    }
                }
            }
#pragma unroll
            for (int i = 0; i < c0.num_elements; i++) c0.x[i] += c1.x[i] + c2.x[i];
            __syncthreads();
            wmma::store_matrix_sync(pbuf + ks * 1024 + m0 * 16, c0, 16, wmma::mem_row_major);
            __syncthreads();

            int b  = tid >> 2;
            int cg = (tid & 3) * 4;
            float4 s0 = *(const float4*)&pbuf[b * 16 + cg];
            float4 s1 = *(const float4*)&pbuf[1024 + b * 16 + cg];
            float s[4] = {s0.x + s1.x, s0.y + s1.y, s0.z + s1.z, s0.w + s1.w};
            int col = n0g + cg;
            if (gate == 0) {
                float4 xg = *(const float4*)&g_xz[(size_t)t * BH + b * HH + col];
                float4 r;
                r.x = 1.f / (1.f + __expf(-(s[0] + xg.x)));
                r.y = 1.f / (1.f + __expf(-(s[1] + xg.y)));
                r.z = 1.f / (1.f + __expf(-(s[2] + xg.z)));
                r.w = 1.f / (1.f + __expf(-(s[3] + xg.w)));
                *(float4*)&g_z[b * HH + col] = r;
            } else {
                float4 xg = *(const float4*)&g_xr[(size_t)t * BH + b * HH + col];
                float4 hv = *(const float4*)&g_h[b * HH + col];
                float rh[4];
                rh[0] = hv.x / (1.f + __expf(-(s[0] + xg.x)));
                rh[1] = hv.y / (1.f + __expf(-(s[1] + xg.y)));
                rh[2] = hv.z / (1.f + __expf(-(s[2] + xg.z)));
                rh[3] = hv.w / (1.f + __expf(-(s[3] + xg.w)));
                union { __nv_bfloat16 h[4]; uint2 u; } HI, LO;
#pragma unroll
                for (int q = 0; q < 4; q++) {
                    __nv_bfloat16 hb16 = __float2bfloat16(rh[q]);
                    HI.h[q] = hb16;
                    LO.h[q] = __float2bfloat16(rh[q] - __bfloat162float(hb16));
                }
                *(uint2*)&g_rh_hi[b * HH + col] = HI.u;
                *(uint2*)&g_rh_lo[b * HH + col] = LO.u;
            }
        }
        grid_barrier();

        // =================== Phase B: candidate, C[32 x 16] ===================
        {
            const int ks = warp >> 1;            // 0..3
            const int wm = warp & 1;
            const int m0 = wm * 16;

            FragC c0, c1, c2;
            wmma::fill_fragment(c0, 0.f);
            wmma::fill_fragment(c1, 0.f);
            wmma::fill_fragment(c2, 0.f);

            uint4 pf[4];
#pragma unroll
            for (int p = 0; p < 2; p++) {
                int row = p * 16 + warp * 2 + rsub;
                size_t off = (size_t)(bh * 32 + row) * HH + kc * 8;
                pf[2*p]   = *(const uint4*)&g_rh_hi[off];
                pf[2*p+1] = *(const uint4*)&g_rh_lo[off];
            }
#pragma unroll
            for (int p = 0; p < 2; p++) {
                int row = p * 16 + warp * 2 + rsub;
                *(uint4*)&hb[row * KPAD + kc * 8]        = pf[2*p];
                *(uint4*)&hb[HMAT + row * KPAD + kc * 8] = pf[2*p+1];
            }

            for (int kt = 0; kt < 8; kt++) {
                __syncthreads();
                if (kt < 7) {
#pragma unroll
                    for (int p = 0; p < 2; p++) {
                        int row = p * 16 + warp * 2 + rsub;
                        size_t off = (size_t)(bh * 32 + row) * HH + (kt+1) * 128 + kc * 8;
                        pf[2*p]   = *(const uint4*)&g_rh_hi[off];
                        pf[2*p+1] = *(const uint4*)&g_rh_lo[off];
                    }
                }
                const __nv_bfloat16* Hh = hb + (kt & 1) * 2 * HMAT;
                const __nv_bfloat16* Hl = Hh + HMAT;
#pragma unroll
                for (int s = 0; s < 2; s++) {
                    int kk = ks * 32 + s * 16;
                    int kg = kt * 128 + kk;
                    FragA ah, al; FragB bhf, blf;
                    wmma::load_matrix_sync(ah, Hh + m0 * KPAD + kk, KPAD);
                    wmma::load_matrix_sync(al, Hl + m0 * KPAD + kk, KPAD);
                    wmma::load_matrix_sync(bhf, wc_h + kg * 16, 16);
                    wmma::load_matrix_sync(blf, wc_l + kg * 16, 16);
                    wmma::mma_sync(c0, ah, bhf, c0);
                    wmma::mma_sync(c1, ah, blf, c1);
                    wmma::mma_sync(c2, al, bhf, c2);
                }
                if (kt < 7) {
                    __nv_bfloat16* Nh = hb + ((kt+1) & 1) * 2 * HMAT;
#pragma unroll
                    for (int p = 0; p < 2; p++) {
                        int row = p * 16 + warp * 2 + rsub;
                        *(uint4*)&Nh[row * KPAD + kc * 8]        = pf[2*p];
                        *(uint4*)&Nh[HMAT + row * KPAD + kc * 8] = pf[2*p+1];
                    }
                }
            }
#pragma unroll
            for (int i = 0; i < c0.num_elements; i++) c0.x[i] += c1.x[i] + c2.x[i];
            __syncthreads();
            wmma::store_matrix_sync(pbuf + ks * 512 + m0 * 16, c0, 16, wmma::mem_row_major);
            __syncthreads();

            int row = tid >> 3;
            int c0i = (tid & 7) * 2;
            float s0 = 0.f, s1 = 0.f;
#pragma unroll
            for (int q = 0; q < 4; q++) {
                s0 += pbuf[q * 512 + row * 16 + c0i + 0];
                s1 += pbuf[q * 512 + row * 16 + c0i + 1];
            }
            int b   = bh * 32 + row;
            int col = n0c + c0i;
            size_t base = (size_t)t * BH + b * HH + col;
            int idx = b * HH + col;
            float xc0 = g_xc[base + 0], xc1 = g_xc[base + 1];
            float z0  = g_z[idx + 0],   z1  = g_z[idx + 1];
            float h0  = g_h[idx + 0],   h1  = g_h[idx + 1];
            float cc0 = tanhf(s0 + xc0);
            float cc1 = tanhf(s1 + xc1);
            float hn0 = (1.f - z0) * h0 + z0 * cc0;
            float hn1 = (1.f - z1) * h1 + z1 * cc1;
            g_h[idx + 0] = hn0; g_h[idx + 1] = hn1;
            out[base + 0] = hn0; out[base + 1] = hn1;
            {
                __nv_bfloat16 h0h = __float2bfloat16(hn0);
                __nv_bfloat16 h1h = __float2bfloat16(hn1);
                __nv_bfloat162 hi2, lo2;
                hi2.x = h0h; hi2.y = h1h;
                lo2.x = __float2bfloat16(hn0 - __bfloat162float(h0h));
                lo2.y = __float2bfloat16(hn1 - __bfloat162float(h1h));
                *(__nv_bfloat162*)&g_h_hi[idx] = hi2;
                *(__nv_bfloat162*)&g_h_lo[idx] = lo2;
            }
            if (t == TT - 1) {
                out[(size_t)TT * BH + idx + 0] = hn0;
                out[(size_t)TT * BH + idx + 1] = hn1;
            }
        }
        grid_barrier();
    }
}

// ---------------- launch ----------------
extern "C" void kernel_launch(void* const* d_in, const int* in_sizes, int n_in,
                              void* d_out, int out_size)
{
    const float* x      = (const float*)d_in[0];
    const float* hidden = (const float*)d_in[1];
    const float* Wzi = (const float*)d_in[2];  const float* bzi = (const float*)d_in[3];
    const float* Wzh = (const float*)d_in[4];  const float* bzh = (const float*)d_in[5];
    const float* Wri = (const float*)d_in[6];  const float* bri = (const float*)d_in[7];
    const float* Wrh = (const float*)d_in[8];  const float* brh = (const float*)d_in[9];
    const float* Wci = (const float*)d_in[10]; const float* bci = (const float*)d_in[11];
    const float* Wch = (const float*)d_in[12]; const float* bch = (const float*)d_in[13];
    float* out = (float*)d_out;

    dim3 gp(HH / BN, (TT * BB) / BM, 3);
    gru_input_proj<<<gp, 256>>>(x, Wzi, bzi, bzh, Wri, bri, brh, Wci, bci, bch);

    cudaFuncSetAttribute(gru_recurrence,
                         cudaFuncAttributeMaxDynamicSharedMemorySize, SMEM_BYTES);
    gru_recurrence<<<NBLK, 256, SMEM_BYTES>>>(hidden, Wzh, Wrh, Wch, out);
}

// round 8
// speedup vs baseline: 2.7490x; 1.2311x over previous
#include <cuda_runtime.h>
#include <cuda_bf16.h>
#include <mma.h>
#include <math.h>

using namespace nvcuda;

#define TT 512
#define BB 64
#define II 1024
#define HH 1024
#define BH (BB*HH)          // 65536
#define NBLK 128            // persistent grid, 1 block/SM

// ---------------- device scratch ----------------
__device__ float g_xz[(size_t)TT*BH];
__device__ float g_xr[(size_t)TT*BH];
__device__ float g_xc[(size_t)TT*BH];
__device__ float g_h[BH];
__device__ float g_z[BH];
__device__ __nv_bfloat16 g_h_hi[BH];
__device__ __nv_bfloat16 g_h_lo[BH];
__device__ __nv_bfloat16 g_rh_hi[BH];
__device__ __nv_bfloat16 g_rh_lo[BH];

// bf16 split mirrors for the input projection
__device__ __nv_bfloat16 g_x_hi[(size_t)TT*BB*II];
__device__ __nv_bfloat16 g_x_lo[(size_t)TT*BB*II];
__device__ __nv_bfloat16 g_wi_hi[(size_t)3*HH*II];
__device__ __nv_bfloat16 g_wi_lo[(size_t)3*HH*II];

// grid barrier: counter zeroed each launch by reset kernel (own graph node)
__device__ unsigned g_arrive = 0;

__global__ void reset_barrier() { g_arrive = 0; }

__device__ __forceinline__ void grid_barrier_t(unsigned target) {
    __syncthreads();
    if (threadIdx.x == 0) {
        __threadfence();
        asm volatile("red.release.gpu.global.add.u32 [%0], %1;"
                     :: "l"(&g_arrive), "r"(1u) : "memory");
        unsigned v;
        do {
            asm volatile("ld.acquire.gpu.global.u32 %0, [%1];"
                         : "=r"(v) : "l"(&g_arrive) : "memory");
        } while (v < target);
    }
    __syncthreads();
}

// ---------------- cp.async helpers ----------------
__device__ __forceinline__ void cpa16(void* s, const void* g) {
    unsigned sa = (unsigned)__cvta_generic_to_shared(s);
    asm volatile("cp.async.cg.shared.global [%0], [%1], 16;" :: "r"(sa), "l"(g));
}
__device__ __forceinline__ void cpa_commit() {
    asm volatile("cp.async.commit_group;");
}
template<int N>
__device__ __forceinline__ void cpa_wait() {
    asm volatile("cp.async.wait_group %0;" :: "n"(N));
}

// ---------------- split conversion kernels ----------------
__global__ void convert_x(const float* __restrict__ x)
{
    size_t i4 = (size_t)blockIdx.x * blockDim.x + threadIdx.x;
    size_t n4 = (size_t)TT * BB * II / 4;
    if (i4 >= n4) return;
    float4 v = *(const float4*)&x[i4 * 4];
    float f[4] = {v.x, v.y, v.z, v.w};
    union { __nv_bfloat16 h[4]; uint2 u; } HI, LO;
#pragma unroll
    for (int q = 0; q < 4; q++) {
        __nv_bfloat16 hv = __float2bfloat16(f[q]);
        HI.h[q] = hv;
        LO.h[q] = __float2bfloat16(f[q] - __bfloat162float(hv));
    }
    *(uint2*)&g_x_hi[i4 * 4] = HI.u;
    *(uint2*)&g_x_lo[i4 * 4] = LO.u;
}

__global__ void convert_w(const float* __restrict__ Wzi,
                          const float* __restrict__ Wri,
                          const float* __restrict__ Wci)
{
    const float* W = (blockIdx.y == 0) ? Wzi : (blockIdx.y == 1) ? Wri : Wci;
    size_t base = (size_t)blockIdx.y * HH * II;
    size_t i4 = (size_t)blockIdx.x * blockDim.x + threadIdx.x;
    if (i4 >= (size_t)HH * II / 4) return;
    float4 v = *(const float4*)&W[i4 * 4];
    float f[4] = {v.x, v.y, v.z, v.w};
    union { __nv_bfloat16 h[4]; uint2 u; } HI, LO;
#pragma unroll
    for (int q = 0; q < 4; q++) {
        __nv_bfloat16 hv = __float2bfloat16(f[q]);
        HI.h[q] = hv;
        LO.h[q] = __float2bfloat16(f[q] - __bfloat162float(hv));
    }
    *(uint2*)&g_wi_hi[base + i4 * 4] = HI.u;
    *(uint2*)&g_wi_lo[base + i4 * 4] = LO.u;
}

// ---------------- tensor-core input projection ----------------
// C[m,n] = x[m,:].W[n,:] + b1[n]+b2[n], bf16-split 3-pass wmma.
// Block tile 128m x 128n, BK=32, cp.async double buffer.
// Warps: 2(m) x 4(n), warp tile 64x32.
#define PM 128
#define PN 128
#define PK 32
#define PKP 40                      // padded k stride (bf16 elems)
#define PMAT (PM*PKP)               // elems per staged matrix
#define PBUF (4*PMAT)               // Ah, Al, Bh, Bl
#define PBIAS_OFF (2*PBUF)          // in bf16 elems
#define PNP 136
#define PSMEM_BYTES (2*PBUF*2 + 16*PNP*4)   // 81920 + 8704 = 90624

typedef wmma::fragment<wmma::matrix_a, 16, 16, 16, __nv_bfloat16, wmma::row_major> PFragA;
typedef wmma::fragment<wmma::matrix_b, 16, 16, 16, __nv_bfloat16, wmma::col_major> PFragB;
typedef wmma::fragment<wmma::accumulator, 16, 16, 16, float> PFragC;

__global__ __launch_bounds__(256)
void gru_input_proj_tc(const float* __restrict__ bzi, const float* __restrict__ bzh,
                       const float* __restrict__ bri, const float* __restrict__ brh,
                       const float* __restrict__ bci, const float* __restrict__ bch)
{
    extern __shared__ __nv_bfloat16 ps[];
    float* bias_sm = (float*)&ps[PBIAS_OFF];

    const int gate = blockIdx.z;
    const float* b1; const float* b2; float* out;
    if (gate == 0)      { b1 = bzi; b2 = bzh; out = g_xz; }
    else if (gate == 1) { b1 = bri; b2 = brh; out = g_xr; }
    else                { b1 = bci; b2 = bch; out = g_xc; }

    const __nv_bfloat16* Wh = g_wi_hi + (size_t)gate * HH * II;
    const __nv_bfloat16* Wl = g_wi_lo + (size_t)gate * HH * II;

    const int m0 = blockIdx.y * PM;
    const int n0 = blockIdx.x * PN;
    const int tid = threadIdx.x;
    const int warp = tid >> 5;
    const int wm = warp >> 2;        // 0..1
    const int wn = warp & 3;         // 0..3

    // bias tile (16 rows replicated)
    for (int idx = tid; idx < 16 * PN; idx += 256) {
        int r = idx >> 7, c = idx & 127;
        bias_sm[r * PNP + c] = b1[n0 + c] + b2[n0 + c];
    }

    // staging coords: row r = tid>>1, k-half = tid&1 (2 x 16B per matrix)
    const int sr = tid >> 1;
    const int sh = tid & 1;

    auto fill = [&](int buf, int k0) {
        __nv_bfloat16* base = ps + buf * PBUF;
#pragma unroll
        for (int i = 0; i < 2; i++) {
            int kc = sh * 16 + i * 8;
            cpa16(&base[sr * PKP + kc],            &g_x_hi[(size_t)(m0 + sr) * II + k0 + kc]);
            cpa16(&base[PMAT + sr * PKP + kc],     &g_x_lo[(size_t)(m0 + sr) * II + k0 + kc]);
            cpa16(&base[2*PMAT + sr * PKP + kc],   &Wh[(size_t)(n0 + sr) * II + k0 + kc]);
            cpa16(&base[3*PMAT + sr * PKP + kc],   &Wl[(size_t)(n0 + sr) * II + k0 + kc]);
        }
        cpa_commit();
    };

    fill(0, 0);
    __syncthreads();   // bias_sm ready

    PFragC c[4][2];
#pragma unroll
    for (int mf = 0; mf < 4; mf++)
#pragma unroll
        for (int nf = 0; nf < 2; nf++)
            wmma::load_matrix_sync(c[mf][nf],
                bias_sm + wn * 32 + nf * 16, PNP, wmma::mem_row_major);

    for (int kt = 0; kt < II / PK; kt++) {
        if (kt < II / PK - 1) fill((kt + 1) & 1, (kt + 1) * PK);
        if (kt < II / PK - 1) cpa_wait<1>(); else cpa_wait<0>();
        __syncthreads();
        const __nv_bfloat16* base = ps + (kt & 1) * PBUF;
        const __nv_bfloat16* Ah = base;
        const __nv_bfloat16* Al = base + PMAT;
        const __nv_bfloat16* Bh = base + 2 * PMAT;
        const __nv_bfloat16* Bl = base + 3 * PMAT;
#pragma unroll
        for (int ks = 0; ks < 2; ks++) {
            PFragA ah[4], al[4];
            PFragB bh[2], bl[2];
#pragma unroll
            for (int mf = 0; mf < 4; mf++) {
                wmma::load_matrix_sync(ah[mf], Ah + (wm * 64 + mf * 16) * PKP + ks * 16, PKP);
                wmma::load_matrix_sync(al[mf], Al + (wm * 64 + mf * 16) * PKP + ks * 16, PKP);
            }
#pragma unroll
            for (int nf = 0; nf < 2; nf++) {
                wmma::load_matrix_sync(bh[nf], Bh + (wn * 32 + nf * 16) * PKP + ks * 16, PKP);
                wmma::load_matrix_sync(bl[nf], Bl + (wn * 32 + nf * 16) * PKP + ks * 16, PKP);
            }
#pragma unroll
            for (int mf = 0; mf < 4; mf++)
#pragma unroll
                for (int nf = 0; nf < 2; nf++) {
                    wmma::mma_sync(c[mf][nf], ah[mf], bh[nf], c[mf][nf]);
                    wmma::mma_sync(c[mf][nf], ah[mf], bl[nf], c[mf][nf]);
                    wmma::mma_sync(c[mf][nf], al[mf], bh[nf], c[mf][nf]);
                }
        }
        __syncthreads();
    }

#pragma unroll
    for (int mf = 0; mf < 4; mf++)
#pragma unroll
        for (int nf = 0; nf < 2; nf++) {
            int m = m0 + wm * 64 + mf * 16;
            int n = n0 + wn * 32 + nf * 16;
            wmma::store_matrix_sync(out + (size_t)m * HH + n, c[mf][nf], HH,
                                    wmma::mem_row_major);
        }
}

// ---------------- tensor-core persistent recurrence (validated R7) ----------------
#define KPAD 136
#define HMAT (64*KPAD)
#define SMEM_BYTES (4*1024*16*2 + 2*2*HMAT*2)   // 200704

typedef wmma::fragment<wmma::matrix_a, 16, 16, 16, __nv_bfloat16, wmma::row_major> FragA;
typedef wmma::fragment<wmma::matrix_b, 16, 16, 16, __nv_bfloat16, wmma::row_major> FragB;
typedef wmma::fragment<wmma::accumulator, 16, 16, 16, float> FragC;

__global__ __launch_bounds__(256, 1)
void gru_recurrence(const float* __restrict__ hidden,
                    const float* __restrict__ Wzh,
                    const float* __restrict__ Wrh,
                    const float* __restrict__ Wch,
                    float* __restrict__ out)
{
    extern __shared__ char smem[];
    __nv_bfloat16* wzr_h = (__nv_bfloat16*)smem;
    __nv_bfloat16* wzr_l = wzr_h + 1024 * 16;
    __nv_bfloat16* wc_h  = wzr_l + 1024 * 16;
    __nv_bfloat16* wc_l  = wc_h  + 1024 * 16;
    __nv_bfloat16* hb    = wc_l  + 1024 * 16;
    float* pbuf = (float*)hb;

    const int tid  = threadIdx.x;
    const int bid  = blockIdx.x;
    const int warp = tid >> 5;
    const int lane = tid & 31;

    const int gate = bid >> 6;
    const int n0g  = (bid & 63) * 16;
    const int n0c  = (bid & 63) * 16;
    const int bh   = bid >> 6;

    unsigned bar_n = 0;

    // ---- one-time: weight slices -> bf16 hi/lo in smem ----
    {
        const float* WA = gate ? Wrh : Wzh;
        int j  = tid >> 4;
        int kc4 = tid & 15;
#pragma unroll
        for (int i = 0; i < 8; i++) {
            int k = i * 128 + kc4 * 8;
            float4 v0 = *(const float4*)&WA[(size_t)(n0g + j) * HH + k];
            float4 v1 = *(const float4*)&WA[(size_t)(n0g + j) * HH + k + 4];
            float f[8] = {v0.x,v0.y,v0.z,v0.w,v1.x,v1.y,v1.z,v1.w};
#pragma unroll
            for (int q = 0; q < 8; q++) {
                __nv_bfloat16 hv = __float2bfloat16(f[q]);
                wzr_h[(k + q) * 16 + j] = hv;
                wzr_l[(k + q) * 16 + j] = __float2bfloat16(f[q] - __bfloat162float(hv));
            }
            float4 w0 = *(const float4*)&Wch[(size_t)(n0c + j) * HH + k];
            float4 w1 = *(const float4*)&Wch[(size_t)(n0c + j) * HH + k + 4];
            float g[8] = {w0.x,w0.y,w0.z,w0.w,w1.x,w1.y,w1.z,w1.w};
#pragma unroll
            for (int q = 0; q < 8; q++) {
                __nv_bfloat16 hv = __float2bfloat16(g[q]);
                wc_h[(k + q) * 16 + j] = hv;
                wc_l[(k + q) * 16 + j] = __float2bfloat16(g[q] - __bfloat162float(hv));
            }
        }
    }

    // ---- init hidden ----
    for (int i = bid * 256 + tid; i < BH; i += NBLK * 256) {
        float v = hidden[i];
        g_h[i] = v;
        __nv_bfloat16 hv = __float2bfloat16(v);
        g_h_hi[i] = hv;
        g_h_lo[i] = __float2bfloat16(v - __bfloat162float(hv));
    }
    bar_n++; grid_barrier_t(bar_n * NBLK);

    const int rsub = lane >> 4;
    const int kc   = lane & 15;

    for (int t = 0; t < TT; t++) {
        // =================== Phase A: z | r, C[64 x 16] ===================
        {
            const int wm = warp >> 1;
            const int ks = warp & 1;
            const int m0 = wm * 16;

            FragC c0, c1, c2;
            wmma::fill_fragment(c0, 0.f);
            wmma::fill_fragment(c1, 0.f);
            wmma::fill_fragment(c2, 0.f);

            uint4 pf[8];
#pragma unroll
            for (int p = 0; p < 4; p++) {
                int row = p * 16 + warp * 2 + rsub;
                pf[2*p]   = *(const uint4*)&g_h_hi[(size_t)row * HH + kc * 8];
                pf[2*p+1] = *(const uint4*)&g_h_lo[(size_t)row * HH + kc * 8];
            }
#pragma unroll
            for (int p = 0; p < 4; p++) {
                int row = p * 16 + warp * 2 + rsub;
                *(uint4*)&hb[row * KPAD + kc * 8]        = pf[2*p];
                *(uint4*)&hb[HMAT + row * KPAD + kc * 8] = pf[2*p+1];
            }

            for (int kt = 0; kt < 8; kt++) {
                __syncthreads();
                if (kt < 7) {
#pragma unroll
                    for (int p = 0; p < 4; p++) {
                        int row = p * 16 + warp * 2 + rsub;
                        size_t off = (size_t)row * HH + (kt+1) * 128 + kc * 8;
                        pf[2*p]   = *(const uint4*)&g_h_hi[off];
                        pf[2*p+1] = *(const uint4*)&g_h_lo[off];
                    }
                }
                const __nv_bfloat16* Hh = hb + (kt & 1) * 2 * HMAT;
                const __nv_bfloat16* Hl = Hh + HMAT;
#pragma unroll
                for (int s = 0; s < 4; s++) {
                    int kk = ks * 64 + s * 16;
                    int kg = kt * 128 + kk;
                    FragA ah, al; FragB bhf, blf;
                    wmma::load_matrix_sync(ah, Hh + m0 * KPAD + kk, KPAD);
                    wmma::load_matrix_sync(al, Hl + m0 * KPAD + kk, KPAD);
                    wmma::load_matrix_sync(bhf, wzr_h + kg * 16, 16);
                    wmma::load_matrix_sync(blf, wzr_l + kg * 16, 16);
                    wmma::mma_sync(c0, ah, bhf, c0);
                    wmma::mma_sync(c1, ah, blf, c1);
                    wmma::mma_sync(c2, al, bhf, c2);
                }
                if (kt < 7) {
                    __nv_bfloat16* Nh = hb + ((kt+1) & 1) * 2 * HMAT;
#pragma unroll
                    for (int p = 0; p < 4; p++) {
                        int row = p * 16 + warp * 2 + rsub;
                        *(uint4*)&Nh[row * KPAD + kc * 8]        = pf[2*p];
                        *(uint4*)&Nh[HMAT + row * KPAD + kc * 8] = pf[2*p+1];
                    }
                }
            }
#pragma unroll
            for (int i = 0; i < c0.num_elements; i++) c0.x[i] += c1.x[i] + c2.x[i];
            __syncthreads();
            wmma::store_matrix_sync(pbuf + ks * 1024 + m0 * 16, c0, 16, wmma::mem_row_major);
            __syncthreads();

            int b  = tid >> 2;
            int cg = (tid & 3) * 4;
            float4 s0 = *(const float4*)&pbuf[b * 16 + cg];
            float4 s1 = *(const float4*)&pbuf[1024 + b * 16 + cg];
            float s[4] = {s0.x + s1.x, s0.y + s1.y, s0.z + s1.z, s0.w + s1.w};
            int col = n0g + cg;
            if (gate == 0) {
                float4 xg = *(const float4*)&g_xz[(size_t)t * BH + b * HH + col];
                float4 r;
                r.x = 1.f / (1.f + __expf(-(s[0] + xg.x)));
                r.y = 1.f / (1.f + __expf(-(s[1] + xg.y)));
                r.z = 1.f / (1.f + __expf(-(s[2] + xg.z)));
                r.w = 1.f / (1.f + __expf(-(s[3] + xg.w)));
                *(float4*)&g_z[b * HH + col] = r;
            } else {
                float4 xg = *(const float4*)&g_xr[(size_t)t * BH + b * HH + col];
                float4 hv = *(const float4*)&g_h[b * HH + col];
                float rh[4];
                rh[0] = hv.x / (1.f + __expf(-(s[0] + xg.x)));
                rh[1] = hv.y / (1.f + __expf(-(s[1] + xg.y)));
                rh[2] = hv.z / (1.f + __expf(-(s[2] + xg.z)));
                rh[3] = hv.w / (1.f + __expf(-(s[3] + xg.w)));
                union { __nv_bfloat16 h[4]; uint2 u; } HI, LO;
#pragma unroll
                for (int q = 0; q < 4; q++) {
                    __nv_bfloat16 hb16 = __float2bfloat16(rh[q]);
                    HI.h[q] = hb16;
                    LO.h[q] = __float2bfloat16(rh[q] - __bfloat162float(hb16));
                }
                *(uint2*)&g_rh_hi[b * HH + col] = HI.u;
                *(uint2*)&g_rh_lo[b * HH + col] = LO.u;
            }
        }
        bar_n++; grid_barrier_t(bar_n * NBLK);

        // =================== Phase B: candidate, C[32 x 16] ===================
        {
            const int ks = warp >> 1;
            const int wm = warp & 1;
            const int m0 = wm * 16;

            FragC c0, c1, c2;
            wmma::fill_fragment(c0, 0.f);
            wmma::fill_fragment(c1, 0.f);
            wmma::fill_fragment(c2, 0.f);

            uint4 pf[4];
#pragma unroll
            for (int p = 0; p < 2; p++) {
                int row = p * 16 + warp * 2 + rsub;
                size_t off = (size_t)(bh * 32 + row) * HH + kc * 8;
                pf[2*p]   = *(const uint4*)&g_rh_hi[off];
                pf[2*p+1] = *(const uint4*)&g_rh_lo[off];
            }
#pragma unroll
            for (int p = 0; p < 2; p++) {
                int row = p * 16 + warp * 2 + rsub;
                *(uint4*)&hb[row * KPAD + kc * 8]        = pf[2*p];
                *(uint4*)&hb[HMAT + row * KPAD + kc * 8] = pf[2*p+1];
            }

            for (int kt = 0; kt < 8; kt++) {
                __syncthreads();
                if (kt < 7) {
#pragma unroll
                    for (int p = 0; p < 2; p++) {
                        int row = p * 16 + warp * 2 + rsub;
                        size_t off = (size_t)(bh * 32 + row) * HH + (kt+1) * 128 + kc * 8;
                        pf[2*p]   = *(const uint4*)&g_rh_hi[off];
                        pf[2*p+1] = *(const uint4*)&g_rh_lo[off];
                    }
                }
                const __nv_bfloat16* Hh = hb + (kt & 1) * 2 * HMAT;
                const __nv_bfloat16* Hl = Hh + HMAT;
#pragma unroll
                for (int s = 0; s < 2; s++) {
                    int kk = ks * 32 + s * 16;
                    int kg = kt * 128 + kk;
                    FragA ah, al; FragB bhf, blf;
                    wmma::load_matrix_sync(ah, Hh + m0 * KPAD + kk, KPAD);
                    wmma::load_matrix_sync(al, Hl + m0 * KPAD + kk, KPAD);
                    wmma::load_matrix_sync(bhf, wc_h + kg * 16, 16);
                    wmma::load_matrix_sync(blf, wc_l + kg * 16, 16);
                    wmma::mma_sync(c0, ah, bhf, c0);
                    wmma::mma_sync(c1, ah, blf, c1);
                    wmma::mma_sync(c2, al, bhf, c2);
                }
                if (kt < 7) {
                    __nv_bfloat16* Nh = hb + ((kt+1) & 1) * 2 * HMAT;
#pragma unroll
                    for (int p = 0; p < 2; p++) {
                        int row = p * 16 + warp * 2 + rsub;
                        *(uint4*)&Nh[row * KPAD + kc * 8]        = pf[2*p];
                        *(uint4*)&Nh[HMAT + row * KPAD + kc * 8] = pf[2*p+1];
                    }
                }
            }
#pragma unroll
            for (int i = 0; i < c0.num_elements; i++) c0.x[i] += c1.x[i] + c2.x[i];
            __syncthreads();
            wmma::store_matrix_sync(pbuf + ks * 512 + m0 * 16, c0, 16, wmma::mem_row_major);
            __syncthreads();

            int row = tid >> 3;
            int c0i = (tid & 7) * 2;
            float s0 = 0.f, s1 = 0.f;
#pragma unroll
            for (int q = 0; q < 4; q++) {
                s0 += pbuf[q * 512 + row * 16 + c0i + 0];
                s1 += pbuf[q * 512 + row * 16 + c0i + 1];
            }
            int b   = bh * 32 + row;
            int col = n0c + c0i;
            size_t base = (size_t)t * BH + b * HH + col;
            int idx = b * HH + col;
            float xc0 = g_xc[base + 0], xc1 = g_xc[base + 1];
            float z0  = g_z[idx + 0],   z1  = g_z[idx + 1];
            float h0  = g_h[idx + 0],   h1  = g_h[idx + 1];
            float cc0 = tanhf(s0 + xc0);
            float cc1 = tanhf(s1 + xc1);
            float hn0 = (1.f - z0) * h0 + z0 * cc0;
            float hn1 = (1.f - z1) * h1 + z1 * cc1;
            g_h[idx + 0] = hn0; g_h[idx + 1] = hn1;
            out[base + 0] = hn0; out[base + 1] = hn1;
            {
                __nv_bfloat16 h0h = __float2bfloat16(hn0);
                __nv_bfloat16 h1h = __float2bfloat16(hn1);
                __nv_bfloat162 hi2, lo2;
                hi2.x = h0h; hi2.y = h1h;
                lo2.x = __float2bfloat16(hn0 - __bfloat162float(h0h));
                lo2.y = __float2bfloat16(hn1 - __bfloat162float(h1h));
                *(__nv_bfloat162*)&g_h_hi[idx] = hi2;
                *(__nv_bfloat162*)&g_h_lo[idx] = lo2;
            }
            if (t == TT - 1) {
                out[(size_t)TT * BH + idx + 0] = hn0;
                out[(size_t)TT * BH + idx + 1] = hn1;
            }
        }
        bar_n++; grid_barrier_t(bar_n * NBLK);
    }
}

// ---------------- launch ----------------
extern "C" void kernel_launch(void* const* d_in, const int* in_sizes, int n_in,
                              void* d_out, int out_size)
{
    const float* x      = (const float*)d_in[0];
    const float* hidden = (const float*)d_in[1];
    const float* Wzi = (const float*)d_in[2];  const float* bzi = (const float*)d_in[3];
    const float* Wzh = (const float*)d_in[4];  const float* bzh = (const float*)d_in[5];
    const float* Wri = (const float*)d_in[6];  const float* bri = (const float*)d_in[7];
    const float* Wrh = (const float*)d_in[8];  const float* brh = (const float*)d_in[9];
    const float* Wci = (const float*)d_in[10]; const float* bci = (const float*)d_in[11];
    const float* Wch = (const float*)d_in[12]; const float* bch = (const float*)d_in[13];
    float* out = (float*)d_out;

    reset_barrier<<<1, 1>>>();

    {
        size_t n4 = (size_t)TT * BB * II / 4;
        int blocks = (int)((n4 + 255) / 256);
        convert_x<<<blocks, 256>>>(x);
    }
    {
        int blocks = (HH * II / 4 + 255) / 256;
        convert_w<<<dim3(blocks, 3), 256>>>(Wzi, Wri, Wci);
    }

    cudaFuncSetAttribute(gru_input_proj_tc,
                         cudaFuncAttributeMaxDynamicSharedMemorySize, PSMEM_BYTES);
    gru_input_proj_tc<<<dim3(HH / PN, (TT * BB) / PM, 3), 256, PSMEM_BYTES>>>(
        bzi, bzh, bri, brh, bci, bch);

    cudaFuncSetAttribute(gru_recurrence,
                         cudaFuncAttributeMaxDynamicSharedMemorySize, SMEM_BYTES);
    gru_recurrence<<<NBLK, 256, SMEM_BYTES>>>(hidden, Wzh, Wrh, Wch, out);
}